// round 1
// baseline (speedup 1.0000x reference)
#include <cuda_runtime.h>
#include <math.h>

#define BB 64
#define TT 50
#define NN 24
#define FF 256
#define HH 256
#define G4H 1024
#define ROWS (BB*NN)   // 1536

// Scratch (device globals; no allocation allowed)
__device__ float g_Xg[(size_t)TT*BB*NN*FF];     // (T,B,N,F) node-mixed input
__device__ float g_XW[(size_t)TT*BB*NN*G4H];    // (T,B,N,4H) precomputed input gates (+both biases)
__device__ float g_h[ROWS*HH];
__device__ float g_c[ROWS*HH];
__device__ float g_Gh[ROWS*HH];
__device__ float g_gates[ROWS*G4H];

// ---------------------------------------------------------------------------
// Node mix over x: Xg[t,b,n,f] = sum_m G[n,m] * x[b,t,m,f]
// grid = T*B blocks, 256 threads
// ---------------------------------------------------------------------------
__global__ __launch_bounds__(256)
void mix_x_kernel(const float* __restrict__ x, const float* __restrict__ G)
{
    __shared__ float xs[NN*FF];
    __shared__ float Gs[NN*NN];
    int bid = blockIdx.x;          // = t*B + b
    int t = bid / BB, b = bid % BB;
    const float* xin = x + ((size_t)(b*TT + t))*NN*FF;
    float* out = g_Xg + (size_t)bid*NN*FF;
    int tid = threadIdx.x;
    for (int i = tid; i < NN*FF; i += 256) xs[i] = xin[i];
    for (int i = tid; i < NN*NN; i += 256) Gs[i] = G[i];
    __syncthreads();
    for (int i = tid; i < NN*FF; i += 256) {
        int n = i >> 8, f = i & 255;
        float acc = 0.f;
        #pragma unroll
        for (int m = 0; m < NN; ++m) acc += Gs[n*NN+m] * xs[m*FF+f];
        out[i] = acc;
    }
}

// ---------------------------------------------------------------------------
// Node mix over h: Gh[b,n,:] = sum_m G[n,m] * h[b,m,:]
// grid = B blocks, 256 threads
// ---------------------------------------------------------------------------
__global__ __launch_bounds__(256)
void mix_h_kernel(const float* __restrict__ G)
{
    __shared__ float hs[NN*HH];
    __shared__ float Gs[NN*NN];
    int b = blockIdx.x;
    int tid = threadIdx.x;
    const float* hin = g_h + (size_t)b*NN*HH;
    float* out = g_Gh + (size_t)b*NN*HH;
    for (int i = tid; i < NN*HH; i += 256) hs[i] = hin[i];
    for (int i = tid; i < NN*NN; i += 256) Gs[i] = G[i];
    __syncthreads();
    for (int i = tid; i < NN*HH; i += 256) {
        int n = i >> 8, f = i & 255;
        float acc = 0.f;
        #pragma unroll
        for (int m = 0; m < NN; ++m) acc += Gs[n*NN+m] * hs[m*HH+f];
        out[i] = acc;
    }
}

// ---------------------------------------------------------------------------
// Generic tiled fp32 GEMM: C[m,n] = act( sum_k A[m,k]*W[n,k] + bias1[n]
//                                        + bias2[n] + addend[m,n] )
// A: (M,K) row-major, W: (N,K) row-major.  BM=BN=64, BK=16, 256 thr, 4x4/thr.
// Requires M%64==0, N%64==0, K%16==0 (all shapes here comply).
// ---------------------------------------------------------------------------
template<int ACT>
__global__ __launch_bounds__(256)
void gemm_kernel(const float* __restrict__ A, const float* __restrict__ W,
                 const float* __restrict__ bias1, const float* __restrict__ bias2,
                 const float* __restrict__ addend,
                 float* __restrict__ C, int M, int N, int K)
{
    const int BM = 64, BN = 64, BK = 16;
    __shared__ float As[BK][BM];   // transposed A tile
    __shared__ float Bs[BK][BN];
    int tid  = threadIdx.x;
    int tcol = tid & 15;           // 0..15 -> n micro
    int trow = tid >> 4;           // 0..15 -> m micro
    int m0 = blockIdx.y * BM, n0 = blockIdx.x * BN;
    float acc[4][4] = {};

    for (int kk = 0; kk < K; kk += BK) {
        // A tile: 64 rows x 16 k, transposed store
        {
            int r  = tid >> 2;
            int c4 = (tid & 3) * 4;
            float4 v = *(const float4*)(A + (size_t)(m0 + r)*K + kk + c4);
            As[c4+0][r] = v.x; As[c4+1][r] = v.y;
            As[c4+2][r] = v.z; As[c4+3][r] = v.w;
        }
        // W tile: Bs[k][n] = W[(n0+n)*K + kk + k]
        {
            int n  = tid >> 2;
            int k4 = (tid & 3) * 4;
            float4 v = *(const float4*)(W + (size_t)(n0 + n)*K + kk + k4);
            Bs[k4+0][n] = v.x; Bs[k4+1][n] = v.y;
            Bs[k4+2][n] = v.z; Bs[k4+3][n] = v.w;
        }
        __syncthreads();
        #pragma unroll
        for (int k = 0; k < BK; ++k) {
            float4 a  = *(const float4*)&As[k][trow*4];
            float4 bv = *(const float4*)&Bs[k][tcol*4];
            float av[4] = {a.x, a.y, a.z, a.w};
            float bw[4] = {bv.x, bv.y, bv.z, bv.w};
            #pragma unroll
            for (int i = 0; i < 4; ++i)
                #pragma unroll
                for (int j = 0; j < 4; ++j)
                    acc[i][j] += av[i] * bw[j];
        }
        __syncthreads();
    }

    #pragma unroll
    for (int i = 0; i < 4; ++i) {
        int m = m0 + trow*4 + i;
        #pragma unroll
        for (int j = 0; j < 4; ++j) {
            int n = n0 + tcol*4 + j;
            float v = acc[i][j];
            if (bias1)  v += bias1[n];
            if (bias2)  v += bias2[n];
            if (addend) v += addend[(size_t)m*N + n];
            if (ACT)    v = tanhf(v);
            C[(size_t)m*N + n] = v;
        }
    }
}

// ---------------------------------------------------------------------------
// LSTM cell elementwise: gates = [i | f | g | o] (each H wide)
// ---------------------------------------------------------------------------
__global__ __launch_bounds__(256)
void lstm_kernel()
{
    int idx = blockIdx.x * blockDim.x + threadIdx.x;   // < ROWS*HH
    int r = idx >> 8, jh = idx & 255;
    const float* g = g_gates + (size_t)r * G4H;
    float gi = g[jh], gf = g[256+jh], gg = g[512+jh], go = g[768+jh];
    float si = 1.f / (1.f + expf(-gi));
    float sf = 1.f / (1.f + expf(-gf));
    float so = 1.f / (1.f + expf(-go));
    float c = sf * g_c[idx] + si * tanhf(gg);
    g_c[idx] = c;
    g_h[idx] = so * tanhf(c);
}

// ---------------------------------------------------------------------------
extern "C" void kernel_launch(void* const* d_in, const int* in_sizes, int n_in,
                              void* d_out, int out_size)
{
    const float* x    = (const float*)d_in[0];
    const float* G    = (const float*)d_in[1];
    const float* W_ih = (const float*)d_in[2];
    const float* b_ih = (const float*)d_in[3];
    const float* W_hh = (const float*)d_in[4];
    const float* b_hh = (const float*)d_in[5];
    const float* W_h1 = (const float*)d_in[6];
    const float* b_h1 = (const float*)d_in[7];
    const float* W_h2 = (const float*)d_in[8];
    const float* b_h2 = (const float*)d_in[9];
    const float* W_fc = (const float*)d_in[10];
    const float* b_fc = (const float*)d_in[11];
    float* out = (float*)d_out;

    float *Xg, *XW, *h, *c, *Gh, *gates;
    cudaGetSymbolAddress((void**)&Xg,    g_Xg);
    cudaGetSymbolAddress((void**)&XW,    g_XW);
    cudaGetSymbolAddress((void**)&h,     g_h);
    cudaGetSymbolAddress((void**)&c,     g_c);
    cudaGetSymbolAddress((void**)&Gh,    g_Gh);
    cudaGetSymbolAddress((void**)&gates, g_gates);

    // 1) Node-mix all inputs:  Xg = G @ x   (layout (T,B,N,F))
    mix_x_kernel<<<BB*TT, 256>>>(x, G);

    // 2) Hoisted input-gate GEMM for ALL timesteps:
    //    XW = Xg @ W_ih^T + b_ih + b_hh     (76800 x 1024, K=256)
    dim3 gBig(G4H/64, (TT*BB*NN)/64);
    gemm_kernel<0><<<gBig, 256>>>(Xg, W_ih, b_ih, b_hh, nullptr,
                                  XW, TT*BB*NN, G4H, FF);

    // 3) h0/c0 from the t=0 slice of Xg (first B*N*F block)
    dim3 gSm(HH/64, ROWS/64);
    gemm_kernel<0><<<gSm, 256>>>(Xg, W_h1, b_h1, nullptr, nullptr, h, ROWS, HH, FF);
    gemm_kernel<0><<<gSm, 256>>>(Xg, W_h2, b_h2, nullptr, nullptr, c, ROWS, HH, FF);

    // 4) Sequential scan: only the h-path remains per step
    dim3 gGt(G4H/64, ROWS/64);
    for (int t = 0; t < TT; ++t) {
        mix_h_kernel<<<BB, 256>>>(G);
        gemm_kernel<0><<<gGt, 256>>>(Gh, W_hh, nullptr, nullptr,
                                     XW + (size_t)t*ROWS*G4H,
                                     gates, ROWS, G4H, HH);
        lstm_kernel<<<(ROWS*HH)/256, 256>>>();
    }

    // 5) Output: tanh( (G h) @ W_fc^T + b_fc )
    mix_h_kernel<<<BB, 256>>>(G);
    gemm_kernel<1><<<gSm, 256>>>(Gh, W_fc, b_fc, nullptr, nullptr, out, ROWS, HH, HH);
}

// round 2
// speedup vs baseline: 1.0023x; 1.0023x over previous
#include <cuda_runtime.h>
#include <math.h>

#define BB 64
#define TT 50
#define NN 24
#define FF 256
#define HH 256
#define G4H 1024
#define ROWS (BB*NN)   // 1536

// Scratch (device globals; no allocation allowed)
__device__ float g_Xg[(size_t)TT*BB*NN*FF];     // (T,B,N,F) node-mixed input
__device__ float g_XW[(size_t)TT*BB*NN*G4H];    // (T,B,N,4H) precomputed input gates (+both biases)
__device__ float g_h[ROWS*HH];
__device__ float g_c[ROWS*HH];
__device__ float g_Gh[ROWS*HH];
__device__ float g_gates[ROWS*G4H];

// ---------------------------------------------------------------------------
// Node mix over x: Xg[t,b,n,f] = sum_m G[n,m] * x[b,t,m,f]
// grid = T*B blocks, 256 threads
// ---------------------------------------------------------------------------
__global__ __launch_bounds__(256)
void mix_x_kernel(const float* __restrict__ x, const float* __restrict__ G)
{
    __shared__ float xs[NN*FF];
    __shared__ float Gs[NN*NN];
    int bid = blockIdx.x;          // = t*B + b
    int t = bid / BB, b = bid % BB;
    const float* xin = x + ((size_t)(b*TT + t))*NN*FF;
    float* out = g_Xg + (size_t)bid*NN*FF;
    int tid = threadIdx.x;
    for (int i = tid; i < NN*FF; i += 256) xs[i] = xin[i];
    for (int i = tid; i < NN*NN; i += 256) Gs[i] = G[i];
    __syncthreads();
    for (int i = tid; i < NN*FF; i += 256) {
        int n = i >> 8, f = i & 255;
        float acc = 0.f;
        #pragma unroll
        for (int m = 0; m < NN; ++m) acc += Gs[n*NN+m] * xs[m*FF+f];
        out[i] = acc;
    }
}

// ---------------------------------------------------------------------------
// Node mix over h: Gh[b,n,:] = sum_m G[n,m] * h[b,m,:]
// grid = B blocks, 256 threads
// ---------------------------------------------------------------------------
__global__ __launch_bounds__(256)
void mix_h_kernel(const float* __restrict__ G)
{
    __shared__ float hs[NN*HH];
    __shared__ float Gs[NN*NN];
    int b = blockIdx.x;
    int tid = threadIdx.x;
    const float* hin = g_h + (size_t)b*NN*HH;
    float* out = g_Gh + (size_t)b*NN*HH;
    for (int i = tid; i < NN*HH; i += 256) hs[i] = hin[i];
    for (int i = tid; i < NN*NN; i += 256) Gs[i] = G[i];
    __syncthreads();
    for (int i = tid; i < NN*HH; i += 256) {
        int n = i >> 8, f = i & 255;
        float acc = 0.f;
        #pragma unroll
        for (int m = 0; m < NN; ++m) acc += Gs[n*NN+m] * hs[m*HH+f];
        out[i] = acc;
    }
}

// ---------------------------------------------------------------------------
// Generic tiled fp32 GEMM: C[m,n] = act( sum_k A[m,k]*W[n,k] + bias1[n]
//                                        + bias2[n] + addend[m,n] )
// A: (M,K) row-major, W: (N,K) row-major.  BM=BN=64, BK=16, 256 thr, 4x4/thr.
// Requires M%64==0, N%64==0, K%16==0 (all shapes here comply).
// ---------------------------------------------------------------------------
template<int ACT>
__global__ __launch_bounds__(256)
void gemm_kernel(const float* __restrict__ A, const float* __restrict__ W,
                 const float* __restrict__ bias1, const float* __restrict__ bias2,
                 const float* __restrict__ addend,
                 float* __restrict__ C, int M, int N, int K)
{
    const int BM = 64, BN = 64, BK = 16;
    __shared__ float As[BK][BM];   // transposed A tile
    __shared__ float Bs[BK][BN];
    int tid  = threadIdx.x;
    int tcol = tid & 15;           // 0..15 -> n micro
    int trow = tid >> 4;           // 0..15 -> m micro
    int m0 = blockIdx.y * BM, n0 = blockIdx.x * BN;
    float acc[4][4] = {};

    for (int kk = 0; kk < K; kk += BK) {
        // A tile: 64 rows x 16 k, transposed store
        {
            int r  = tid >> 2;
            int c4 = (tid & 3) * 4;
            float4 v = *(const float4*)(A + (size_t)(m0 + r)*K + kk + c4);
            As[c4+0][r] = v.x; As[c4+1][r] = v.y;
            As[c4+2][r] = v.z; As[c4+3][r] = v.w;
        }
        // W tile: Bs[k][n] = W[(n0+n)*K + kk + k]
        {
            int n  = tid >> 2;
            int k4 = (tid & 3) * 4;
            float4 v = *(const float4*)(W + (size_t)(n0 + n)*K + kk + k4);
            Bs[k4+0][n] = v.x; Bs[k4+1][n] = v.y;
            Bs[k4+2][n] = v.z; Bs[k4+3][n] = v.w;
        }
        __syncthreads();
        #pragma unroll
        for (int k = 0; k < BK; ++k) {
            float4 a  = *(const float4*)&As[k][trow*4];
            float4 bv = *(const float4*)&Bs[k][tcol*4];
            float av[4] = {a.x, a.y, a.z, a.w};
            float bw[4] = {bv.x, bv.y, bv.z, bv.w};
            #pragma unroll
            for (int i = 0; i < 4; ++i)
                #pragma unroll
                for (int j = 0; j < 4; ++j)
                    acc[i][j] += av[i] * bw[j];
        }
        __syncthreads();
    }

    #pragma unroll
    for (int i = 0; i < 4; ++i) {
        int m = m0 + trow*4 + i;
        #pragma unroll
        for (int j = 0; j < 4; ++j) {
            int n = n0 + tcol*4 + j;
            float v = acc[i][j];
            if (bias1)  v += bias1[n];
            if (bias2)  v += bias2[n];
            if (addend) v += addend[(size_t)m*N + n];
            if (ACT)    v = tanhf(v);
            C[(size_t)m*N + n] = v;
        }
    }
}

// ---------------------------------------------------------------------------
// LSTM cell elementwise: gates = [i | f | g | o] (each H wide)
// ---------------------------------------------------------------------------
__global__ __launch_bounds__(256)
void lstm_kernel()
{
    int idx = blockIdx.x * blockDim.x + threadIdx.x;   // < ROWS*HH
    int r = idx >> 8, jh = idx & 255;
    const float* g = g_gates + (size_t)r * G4H;
    float gi = g[jh], gf = g[256+jh], gg = g[512+jh], go = g[768+jh];
    float si = 1.f / (1.f + expf(-gi));
    float sf = 1.f / (1.f + expf(-gf));
    float so = 1.f / (1.f + expf(-go));
    float c = sf * g_c[idx] + si * tanhf(gg);
    g_c[idx] = c;
    g_h[idx] = so * tanhf(c);
}

// ---------------------------------------------------------------------------
extern "C" void kernel_launch(void* const* d_in, const int* in_sizes, int n_in,
                              void* d_out, int out_size)
{
    const float* x    = (const float*)d_in[0];
    const float* G    = (const float*)d_in[1];
    const float* W_ih = (const float*)d_in[2];
    const float* b_ih = (const float*)d_in[3];
    const float* W_hh = (const float*)d_in[4];
    const float* b_hh = (const float*)d_in[5];
    const float* W_h1 = (const float*)d_in[6];
    const float* b_h1 = (const float*)d_in[7];
    const float* W_h2 = (const float*)d_in[8];
    const float* b_h2 = (const float*)d_in[9];
    const float* W_fc = (const float*)d_in[10];
    const float* b_fc = (const float*)d_in[11];
    float* out = (float*)d_out;

    float *Xg, *XW, *h, *c, *Gh, *gates;
    cudaGetSymbolAddress((void**)&Xg,    g_Xg);
    cudaGetSymbolAddress((void**)&XW,    g_XW);
    cudaGetSymbolAddress((void**)&h,     g_h);
    cudaGetSymbolAddress((void**)&c,     g_c);
    cudaGetSymbolAddress((void**)&Gh,    g_Gh);
    cudaGetSymbolAddress((void**)&gates, g_gates);

    // 1) Node-mix all inputs:  Xg = G @ x   (layout (T,B,N,F))
    mix_x_kernel<<<BB*TT, 256>>>(x, G);

    // 2) Hoisted input-gate GEMM for ALL timesteps:
    //    XW = Xg @ W_ih^T + b_ih + b_hh     (76800 x 1024, K=256)
    dim3 gBig(G4H/64, (TT*BB*NN)/64);
    gemm_kernel<0><<<gBig, 256>>>(Xg, W_ih, b_ih, b_hh, nullptr,
                                  XW, TT*BB*NN, G4H, FF);

    // 3) h0/c0 from the t=0 slice of Xg (first B*N*F block)
    dim3 gSm(HH/64, ROWS/64);
    gemm_kernel<0><<<gSm, 256>>>(Xg, W_h1, b_h1, nullptr, nullptr, h, ROWS, HH, FF);
    gemm_kernel<0><<<gSm, 256>>>(Xg, W_h2, b_h2, nullptr, nullptr, c, ROWS, HH, FF);

    // 4) Sequential scan: only the h-path remains per step
    dim3 gGt(G4H/64, ROWS/64);
    for (int t = 0; t < TT; ++t) {
        mix_h_kernel<<<BB, 256>>>(G);
        gemm_kernel<0><<<gGt, 256>>>(Gh, W_hh, nullptr, nullptr,
                                     XW + (size_t)t*ROWS*G4H,
                                     gates, ROWS, G4H, HH);
        lstm_kernel<<<(ROWS*HH)/256, 256>>>();
    }

    // 5) Output: tanh( (G h) @ W_fc^T + b_fc )
    mix_h_kernel<<<BB, 256>>>(G);
    gemm_kernel<1><<<gSm, 256>>>(Gh, W_fc, b_fc, nullptr, nullptr, out, ROWS, HH, HH);
}

// round 3
// speedup vs baseline: 1.5125x; 1.5090x over previous
#include <cuda_runtime.h>
#include <cuda_bf16.h>
#include <math.h>
#include <stdint.h>

#define BB 64
#define TT 50
#define NN 24
#define FF 256
#define HH 256
#define G4H 1024
#define ROWS (BB*NN)   // 1536
#define KCAT 512
#define SKP 40         // padded bf16 smem row stride (80B = 5*16B, conflict-free)

// ------------------ device scratch (no allocations allowed) ----------------
__device__ __nv_bfloat16 g_Xh[(size_t)TT*ROWS*FF];   // node-mixed x, bf16 hi
__device__ __nv_bfloat16 g_Xl[(size_t)TT*ROWS*FF];   // residual lo
__device__ __nv_bfloat16 g_Ghh[ROWS*HH];             // node-mixed h, hi
__device__ __nv_bfloat16 g_Ghl[ROWS*HH];
__device__ __nv_bfloat16 g_Wch[(size_t)G4H*KCAT];    // packed [W_ih|W_hh], gate-interleaved
__device__ __nv_bfloat16 g_Wcl[(size_t)G4H*KCAT];
__device__ __nv_bfloat16 g_W1h[HH*FF], g_W1l[HH*FF];
__device__ __nv_bfloat16 g_W2h[HH*FF], g_W2l[HH*FF];
__device__ __nv_bfloat16 g_Wfh[HH*HH], g_Wfl[HH*HH];
__device__ float g_bcat[G4H];                        // b_ih+b_hh, interleaved order
__device__ float g_h[ROWS*HH];
__device__ float g_c[ROWS*HH];

// ------------------ helpers ------------------------------------------------
__device__ __forceinline__ float sigf(float x) { return 1.f / (1.f + __expf(-x)); }

__device__ __forceinline__ void mma16816(float* d, const unsigned* a, const unsigned* b) {
    asm volatile("mma.sync.aligned.m16n8k16.row.col.f32.bf16.bf16.f32 "
                 "{%0,%1,%2,%3},{%4,%5,%6,%7},{%8,%9},{%0,%1,%2,%3};"
                 : "+f"(d[0]), "+f"(d[1]), "+f"(d[2]), "+f"(d[3])
                 : "r"(a[0]), "r"(a[1]), "r"(a[2]), "r"(a[3]),
                   "r"(b[0]), "r"(b[1]));
}

__device__ __forceinline__ void ldsm4(unsigned* r, const __nv_bfloat16* p) {
    unsigned addr = (unsigned)__cvta_generic_to_shared(p);
    asm volatile("ldmatrix.sync.aligned.m8n8.x4.shared.b16 {%0,%1,%2,%3},[%4];"
                 : "=r"(r[0]), "=r"(r[1]), "=r"(r[2]), "=r"(r[3]) : "r"(addr));
}

// ------------------ packing kernels ----------------------------------------
// packed col n = 4*j + q ; original weight row r = q*256 + j  (q: i,f,g,o)
__global__ __launch_bounds__(256)
void pack_cat(const float* __restrict__ Wih, const float* __restrict__ Whh,
              const float* __restrict__ bih, const float* __restrict__ bhh)
{
    int idx = blockIdx.x * 256 + threadIdx.x;       // over G4H*KCAT
    int n = idx >> 9, k = idx & 511;
    int r = (n & 3) * HH + (n >> 2);
    float v = (k < 256) ? Wih[r*256 + k] : Whh[r*256 + (k - 256)];
    __nv_bfloat16 hv = __float2bfloat16(v);
    g_Wch[idx] = hv;
    g_Wcl[idx] = __float2bfloat16(v - __bfloat162float(hv));
    if (k == 0) g_bcat[n] = bih[r] + bhh[r];
}

__global__ __launch_bounds__(256)
void pack_w(const float* __restrict__ W, __nv_bfloat16* __restrict__ Wh,
            __nv_bfloat16* __restrict__ Wl)
{
    int idx = blockIdx.x * 256 + threadIdx.x;       // over 65536
    float v = W[idx];
    __nv_bfloat16 hv = __float2bfloat16(v);
    Wh[idx] = hv;
    Wl[idx] = __float2bfloat16(v - __bfloat162float(hv));
}

// ------------------ node-mix kernels (fp32 compute, bf16 hi/lo out) --------
__global__ __launch_bounds__(256)
void mix_x(const float* __restrict__ x, const float* __restrict__ G)
{
    __shared__ float xs[NN*FF];
    __shared__ float Gs[NN*NN];
    int bid = blockIdx.x, t = bid / BB, b = bid % BB;
    const float* xin = x + (size_t)(b*TT + t) * NN * FF;
    size_t ob = (size_t)bid * NN * FF;
    int tid = threadIdx.x;
    for (int i = tid; i < NN*FF; i += 256) xs[i] = xin[i];
    for (int i = tid; i < NN*NN; i += 256) Gs[i] = G[i];
    __syncthreads();
    for (int i = tid; i < NN*FF; i += 256) {
        int n = i >> 8, f = i & 255;
        float a = 0.f;
        #pragma unroll
        for (int m = 0; m < NN; ++m) a += Gs[n*NN + m] * xs[m*FF + f];
        __nv_bfloat16 hv = __float2bfloat16(a);
        g_Xh[ob + i] = hv;
        g_Xl[ob + i] = __float2bfloat16(a - __bfloat162float(hv));
    }
}

__global__ __launch_bounds__(256)
void mix_h(const float* __restrict__ G)
{
    __shared__ float hs[NN*HH];
    __shared__ float Gs[NN*NN];
    int b = blockIdx.x, tid = threadIdx.x;
    const float* hin = g_h + (size_t)b * NN * HH;
    size_t ob = (size_t)b * NN * HH;
    for (int i = tid; i < NN*HH; i += 256) hs[i] = hin[i];
    for (int i = tid; i < NN*NN; i += 256) Gs[i] = G[i];
    __syncthreads();
    for (int i = tid; i < NN*HH; i += 256) {
        int n = i >> 8, f = i & 255;
        float a = 0.f;
        #pragma unroll
        for (int m = 0; m < NN; ++m) a += Gs[n*NN + m] * hs[m*HH + f];
        __nv_bfloat16 hv = __float2bfloat16(a);
        g_Ghh[ob + i] = hv;
        g_Ghl[ob + i] = __float2bfloat16(a - __bfloat162float(hv));
    }
}

// ------------------ split-precision bf16 tensor-core GEMM ------------------
// C = A @ B^T where A = A_hi+A_lo (rows M, lda=256; for MODE0 the K range
// [256,512) comes from A2 = node-mixed h), B = B_hi+B_lo ((N,K) row-major).
// MODE 0: N=1024 gate-interleaved, fused LSTM cell epilogue (writes h,c)
// MODE 1: C + bias -> fp32 Out1
// MODE 2: tanh(C + bias) -> fp32 Out1
// Block tile 128x64, 8 warps (4x2), warp tile 32x32, K-step 32.
template<int MODE>
__global__ __launch_bounds__(256)
void mma_gemm(const __nv_bfloat16* __restrict__ A1h, const __nv_bfloat16* __restrict__ A1l,
              const __nv_bfloat16* __restrict__ A2h, const __nv_bfloat16* __restrict__ A2l,
              const __nv_bfloat16* __restrict__ Bh0, const __nv_bfloat16* __restrict__ Bl0,
              const float* __restrict__ bias,
              float* __restrict__ Out1, float* __restrict__ Out2,
              int K, int Nn, int ldb)
{
    extern __shared__ char sm_raw[];
    __nv_bfloat16* sAh = (__nv_bfloat16*)sm_raw;       // 128*SKP
    __nv_bfloat16* sAl = sAh + 128*SKP;
    __nv_bfloat16* sBh = sAl + 128*SKP;                // 64*SKP
    __nv_bfloat16* sBl = sBh + 64*SKP;
    float* Cs = (float*)sm_raw;                        // 128*72 (overlaps A/B)

    int tid = threadIdx.x;
    int lane = tid & 31, warp = tid >> 5;
    int wm = warp >> 1, wn = warp & 1;
    int m0 = blockIdx.y * 128, n0 = blockIdx.x * 64;

    float acc[2][4][4];
    #pragma unroll
    for (int i = 0; i < 2; ++i)
        #pragma unroll
        for (int j = 0; j < 4; ++j)
            #pragma unroll
            for (int e = 0; e < 4; ++e) acc[i][j][e] = 0.f;

    int ar = tid >> 1;             // A row 0..127
    int ak = (tid & 1) * 16;       // A k-offset {0,16}
    int br = tid >> 2;             // B row 0..63
    int bk = (tid & 3) * 8;        // B k-offset

    for (int kk = 0; kk < K; kk += 32) {
        const __nv_bfloat16* pAh = A1h;
        const __nv_bfloat16* pAl = A1l;
        int kl = kk;
        if (MODE == 0 && kk >= 256) { pAh = A2h; pAl = A2l; kl = kk - 256; }

        const __nv_bfloat16* gAh = pAh + (size_t)(m0 + ar)*256 + kl + ak;
        const __nv_bfloat16* gAl = pAl + (size_t)(m0 + ar)*256 + kl + ak;
        *(uint4*)&sAh[ar*SKP + ak]      = *(const uint4*)gAh;
        *(uint4*)&sAh[ar*SKP + ak + 8]  = *(const uint4*)(gAh + 8);
        *(uint4*)&sAl[ar*SKP + ak]      = *(const uint4*)gAl;
        *(uint4*)&sAl[ar*SKP + ak + 8]  = *(const uint4*)(gAl + 8);
        *(uint4*)&sBh[br*SKP + bk] = *(const uint4*)(Bh0 + (size_t)(n0 + br)*ldb + kk + bk);
        *(uint4*)&sBl[br*SKP + bk] = *(const uint4*)(Bl0 + (size_t)(n0 + br)*ldb + kk + bk);
        __syncthreads();

        #pragma unroll
        for (int kq = 0; kq < 32; kq += 16) {
            unsigned ah[2][4], al[2][4], bh[4][2], bl[4][2];
            #pragma unroll
            for (int i = 0; i < 2; ++i) {
                int row = wm*32 + i*16 + (lane & 15);
                int col = kq + ((lane >> 4) << 3);
                ldsm4(ah[i], &sAh[row*SKP + col]);
                ldsm4(al[i], &sAl[row*SKP + col]);
            }
            #pragma unroll
            for (int j = 0; j < 4; ++j) {
                int n = wn*32 + j*8 + (lane >> 2);
                int k = kq + (lane & 3)*2;
                bh[j][0] = *(const unsigned*)&sBh[n*SKP + k];
                bh[j][1] = *(const unsigned*)&sBh[n*SKP + k + 8];
                bl[j][0] = *(const unsigned*)&sBl[n*SKP + k];
                bl[j][1] = *(const unsigned*)&sBl[n*SKP + k + 8];
            }
            #pragma unroll
            for (int i = 0; i < 2; ++i)
                #pragma unroll
                for (int j = 0; j < 4; ++j) {
                    mma16816(acc[i][j], ah[i], bh[j]);
                    mma16816(acc[i][j], al[i], bh[j]);
                    mma16816(acc[i][j], ah[i], bl[j]);
                }
        }
        __syncthreads();
    }

    // stage accumulators through smem (Cs row stride 72 floats = 288B, 16B mult)
    #pragma unroll
    for (int i = 0; i < 2; ++i) {
        int r = wm*32 + i*16 + (lane >> 2);
        #pragma unroll
        for (int j = 0; j < 4; ++j) {
            int cc = wn*32 + j*8 + (lane & 3)*2;
            Cs[r*72 + cc]         = acc[i][j][0];
            Cs[r*72 + cc + 1]     = acc[i][j][1];
            Cs[(r+8)*72 + cc]     = acc[i][j][2];
            Cs[(r+8)*72 + cc + 1] = acc[i][j][3];
        }
    }
    __syncthreads();

    if (MODE == 0) {
        // fused LSTM cell: 16 h-units per block column tile
        for (int idx = tid; idx < 128*16; idx += 256) {
            int r = idx >> 4, u = idx & 15;
            float4 gv = *(const float4*)&Cs[r*72 + u*4];
            int nb = n0 + u*4;
            float vi = sigf (gv.x + bias[nb + 0]);
            float vf = sigf (gv.y + bias[nb + 1]);
            float vg = tanhf(gv.z + bias[nb + 2]);
            float vo = sigf (gv.w + bias[nb + 3]);
            int off = (m0 + r)*HH + (n0 >> 2) + u;
            float c = vf * Out2[off] + vi * vg;
            Out2[off] = c;
            Out1[off] = vo * tanhf(c);
        }
    } else {
        for (int idx = tid; idx < 128*64; idx += 256) {
            int r = idx >> 6, cc = idx & 63;
            float v = Cs[r*72 + cc] + bias[n0 + cc];
            if (MODE == 2) v = tanhf(v);
            Out1[(size_t)(m0 + r)*Nn + n0 + cc] = v;
        }
    }
}

// ---------------------------------------------------------------------------
extern "C" void kernel_launch(void* const* d_in, const int* in_sizes, int n_in,
                              void* d_out, int out_size)
{
    const float* x    = (const float*)d_in[0];
    const float* G    = (const float*)d_in[1];
    const float* W_ih = (const float*)d_in[2];
    const float* b_ih = (const float*)d_in[3];
    const float* W_hh = (const float*)d_in[4];
    const float* b_hh = (const float*)d_in[5];
    const float* W_h1 = (const float*)d_in[6];
    const float* b_h1 = (const float*)d_in[7];
    const float* W_h2 = (const float*)d_in[8];
    const float* b_h2 = (const float*)d_in[9];
    const float* W_fc = (const float*)d_in[10];
    const float* b_fc = (const float*)d_in[11];
    float* out = (float*)d_out;

    __nv_bfloat16 *Xh, *Xl, *Ghh, *Ghl, *Wch, *Wcl, *W1h, *W1l, *W2h, *W2l, *Wfh, *Wfl;
    float *bcat, *h, *c;
    cudaGetSymbolAddress((void**)&Xh,  g_Xh);
    cudaGetSymbolAddress((void**)&Xl,  g_Xl);
    cudaGetSymbolAddress((void**)&Ghh, g_Ghh);
    cudaGetSymbolAddress((void**)&Ghl, g_Ghl);
    cudaGetSymbolAddress((void**)&Wch, g_Wch);
    cudaGetSymbolAddress((void**)&Wcl, g_Wcl);
    cudaGetSymbolAddress((void**)&W1h, g_W1h);
    cudaGetSymbolAddress((void**)&W1l, g_W1l);
    cudaGetSymbolAddress((void**)&W2h, g_W2h);
    cudaGetSymbolAddress((void**)&W2l, g_W2l);
    cudaGetSymbolAddress((void**)&Wfh, g_Wfh);
    cudaGetSymbolAddress((void**)&Wfl, g_Wfl);
    cudaGetSymbolAddress((void**)&bcat, g_bcat);
    cudaGetSymbolAddress((void**)&h,   g_h);
    cudaGetSymbolAddress((void**)&c,   g_c);

    const size_t SMSZ = 128*72*sizeof(float);   // 36864 > A/B staging (30720)

    // prep: node-mix all inputs, pack all weights to bf16 hi/lo
    mix_x<<<BB*TT, 256>>>(x, G);
    pack_cat<<<(G4H*KCAT)/256, 256>>>(W_ih, W_hh, b_ih, b_hh);
    pack_w<<<(HH*FF)/256, 256>>>(W_h1, W1h, W1l);
    pack_w<<<(HH*FF)/256, 256>>>(W_h2, W2h, W2l);
    pack_w<<<(HH*HH)/256, 256>>>(W_fc, Wfh, Wfl);

    // h0 / c0 from t=0 slice of node-mixed x
    dim3 gSm(4, 12);
    mma_gemm<1><<<gSm, 256, SMSZ>>>(Xh, Xl, nullptr, nullptr, W1h, W1l, b_h1,
                                    h, nullptr, 256, 256, 256);
    mma_gemm<1><<<gSm, 256, SMSZ>>>(Xh, Xl, nullptr, nullptr, W2h, W2l, b_h2,
                                    c, nullptr, 256, 256, 256);

    // scan: mix_h -> fused concat-K GEMM + LSTM cell
    dim3 gCell(16, 12);
    for (int t = 0; t < TT; ++t) {
        mix_h<<<BB, 256>>>(G);
        mma_gemm<0><<<gCell, 256, SMSZ>>>(Xh + (size_t)t*ROWS*FF, Xl + (size_t)t*ROWS*FF,
                                          Ghh, Ghl, Wch, Wcl, bcat,
                                          h, c, KCAT, G4H, KCAT);
    }

    // output: tanh((G h) @ W_fc^T + b_fc)
    mix_h<<<BB, 256>>>(G);
    mma_gemm<2><<<gSm, 256, SMSZ>>>(Ghh, Ghl, nullptr, nullptr, Wfh, Wfl, b_fc,
                                    out, nullptr, 256, 256, 256);
}

// round 4
// speedup vs baseline: 2.0332x; 1.3443x over previous
#include <cuda_runtime.h>
#include <cuda_bf16.h>
#include <math.h>
#include <stdint.h>

#define BB 64
#define TT 50
#define NN 24
#define FF 256
#define HH 256
#define G4H 1024
#define ROWS (BB*NN)   // 1536
#define KCAT 512
#define SKP 40         // padded bf16 smem row stride
#define THREADS 192    // 6 warps: 3x2, warp tile 32x32, block tile 96x64

// ------------------ device scratch (no allocations allowed) ----------------
__device__ __nv_bfloat16 g_Xh[(size_t)TT*ROWS*FF];
__device__ __nv_bfloat16 g_Xl[(size_t)TT*ROWS*FF];
__device__ __nv_bfloat16 g_Ghh[2][ROWS*HH];          // ping-pong node-mixed h
__device__ __nv_bfloat16 g_Ghl[2][ROWS*HH];
__device__ __nv_bfloat16 g_Wch[(size_t)G4H*KCAT];    // [W_ih|W_hh], gate-interleaved
__device__ __nv_bfloat16 g_Wcl[(size_t)G4H*KCAT];
__device__ __nv_bfloat16 g_W1h[HH*FF], g_W1l[HH*FF];
__device__ __nv_bfloat16 g_W2h[HH*FF], g_W2l[HH*FF];
__device__ __nv_bfloat16 g_Wfh[HH*HH], g_Wfl[HH*HH];
__device__ float g_bcat[G4H];
__device__ float g_h[ROWS*HH];
__device__ float g_c[ROWS*HH];

// ------------------ helpers ------------------------------------------------
__device__ __forceinline__ float sigf(float x) { return 1.f / (1.f + __expf(-x)); }
__device__ __forceinline__ float tanh_fast(float x) {
    float ax = fabsf(x);
    float t = __expf(-2.f * ax);
    float r = (1.f - t) / (1.f + t);
    return copysignf(r, x);
}

__device__ __forceinline__ void mma16816(float* d, const unsigned* a, const unsigned* b) {
    asm volatile("mma.sync.aligned.m16n8k16.row.col.f32.bf16.bf16.f32 "
                 "{%0,%1,%2,%3},{%4,%5,%6,%7},{%8,%9},{%0,%1,%2,%3};"
                 : "+f"(d[0]), "+f"(d[1]), "+f"(d[2]), "+f"(d[3])
                 : "r"(a[0]), "r"(a[1]), "r"(a[2]), "r"(a[3]),
                   "r"(b[0]), "r"(b[1]));
}
__device__ __forceinline__ void ldsm4(unsigned* r, const __nv_bfloat16* p) {
    unsigned addr = (unsigned)__cvta_generic_to_shared(p);
    asm volatile("ldmatrix.sync.aligned.m8n8.x4.shared.b16 {%0,%1,%2,%3},[%4];"
                 : "=r"(r[0]), "=r"(r[1]), "=r"(r[2]), "=r"(r[3]) : "r"(addr));
}

// ------------------ packing -------------------------------------------------
// packed col n = 4*j + q ; original weight row r = q*256 + j  (q: i,f,g,o)
__global__ __launch_bounds__(256)
void pack_cat(const float* __restrict__ Wih, const float* __restrict__ Whh,
              const float* __restrict__ bih, const float* __restrict__ bhh)
{
    int idx = blockIdx.x * 256 + threadIdx.x;
    int n = idx >> 9, k = idx & 511;
    int r = (n & 3) * HH + (n >> 2);
    float v = (k < 256) ? Wih[r*256 + k] : Whh[r*256 + (k - 256)];
    __nv_bfloat16 hv = __float2bfloat16(v);
    g_Wch[idx] = hv;
    g_Wcl[idx] = __float2bfloat16(v - __bfloat162float(hv));
    if (k == 0) g_bcat[n] = bih[r] + bhh[r];
}

__global__ __launch_bounds__(256)
void pack_w(const float* __restrict__ W, __nv_bfloat16* __restrict__ Wh,
            __nv_bfloat16* __restrict__ Wl)
{
    int idx = blockIdx.x * 256 + threadIdx.x;
    float v = W[idx];
    __nv_bfloat16 hv = __float2bfloat16(v);
    Wh[idx] = hv;
    Wl[idx] = __float2bfloat16(v - __bfloat162float(hv));
}

// ------------------ node-mix kernels ----------------------------------------
__global__ __launch_bounds__(256)
void mix_x(const float* __restrict__ x, const float* __restrict__ G)
{
    __shared__ float xs[NN*FF];
    __shared__ float Gs[NN*NN];
    int bid = blockIdx.x, t = bid / BB, b = bid % BB;
    const float* xin = x + (size_t)(b*TT + t) * NN * FF;
    size_t ob = (size_t)bid * NN * FF;
    int tid = threadIdx.x;
    for (int i = tid; i < NN*FF; i += 256) xs[i] = xin[i];
    for (int i = tid; i < NN*NN; i += 256) Gs[i] = G[i];
    __syncthreads();
    for (int i = tid; i < NN*FF; i += 256) {
        int n = i >> 8, f = i & 255;
        float a = 0.f;
        #pragma unroll
        for (int m = 0; m < NN; ++m) a += Gs[n*NN + m] * xs[m*FF + f];
        __nv_bfloat16 hv = __float2bfloat16(a);
        g_Xh[ob + i] = hv;
        g_Xl[ob + i] = __float2bfloat16(a - __bfloat162float(hv));
    }
}

// one-shot mix of h0 into the given Gh buffer
__global__ __launch_bounds__(256)
void mix_h(const float* __restrict__ G, __nv_bfloat16* __restrict__ oh,
           __nv_bfloat16* __restrict__ ol)
{
    __shared__ float hs[NN*HH];
    __shared__ float Gs[NN*NN];
    int b = blockIdx.x, tid = threadIdx.x;
    const float* hin = g_h + (size_t)b * NN * HH;
    size_t ob = (size_t)b * NN * HH;
    for (int i = tid; i < NN*HH; i += 256) hs[i] = hin[i];
    for (int i = tid; i < NN*NN; i += 256) Gs[i] = G[i];
    __syncthreads();
    for (int i = tid; i < NN*HH; i += 256) {
        int n = i >> 8, f = i & 255;
        float a = 0.f;
        #pragma unroll
        for (int m = 0; m < NN; ++m) a += Gs[n*NN + m] * hs[m*HH + f];
        __nv_bfloat16 hv = __float2bfloat16(a);
        oh[ob + i] = hv;
        ol[ob + i] = __float2bfloat16(a - __bfloat162float(hv));
    }
}

// ------------------ split-precision tensor-core GEMM (96x64 block tile) -----
// MODE 0: gates = [A1|A2] @ Wcat^T, fused LSTM cell + G node-mix epilogue
//         (writes c in-place, writes GoH/GoL bf16 hi/lo of G@h_new)
// MODE 1: OutF = C + bias
// MODE 2: OutF = tanh(C + bias)
template<int MODE>
__global__ __launch_bounds__(THREADS)
void mma_gemm(const __nv_bfloat16* __restrict__ A1h, const __nv_bfloat16* __restrict__ A1l,
              const __nv_bfloat16* __restrict__ A2h, const __nv_bfloat16* __restrict__ A2l,
              const __nv_bfloat16* __restrict__ Bh0, const __nv_bfloat16* __restrict__ Bl0,
              const float* __restrict__ bias, const float* __restrict__ Gmat,
              float* __restrict__ OutF, float* __restrict__ Cmem,
              __nv_bfloat16* __restrict__ GoH, __nv_bfloat16* __restrict__ GoL,
              int K, int Nn, int ldb)
{
    extern __shared__ char sm_raw[];
    float* sG = (float*)sm_raw;                    // 576 floats
    char* base = sm_raw + 2304;
    __nv_bfloat16* sAh = (__nv_bfloat16*)base;     // 96*SKP
    __nv_bfloat16* sAl = sAh + 96*SKP;
    __nv_bfloat16* sBh = sAl + 96*SKP;             // 64*SKP
    __nv_bfloat16* sBl = sBh + 64*SKP;
    float* Cs = (float*)base;                      // 96*72 (overlaps staging)
    float* Hs = Cs + 96*72;                        // 96*17

    int tid = threadIdx.x, lane = tid & 31, warp = tid >> 5;
    int wm = warp >> 1, wn = warp & 1;
    int m0 = blockIdx.y * 96, n0 = blockIdx.x * 64;

    if (MODE == 0)
        for (int i = tid; i < NN*NN; i += THREADS) sG[i] = Gmat[i];

    float acc[2][4][4] = {};

    int ar = tid >> 1, ak = (tid & 1) * 16;        // A: 96 rows x 32 k
    int br = tid >> 1, bk = (tid & 1) * 16;        // B: 64 rows x 32 k (tid<128)
    bool doB = tid < 128;
    uint4 pa0, pa1, pa2, pa3, pb0, pb1, pb2, pb3;

    auto fetch = [&](int kk) {
        const __nv_bfloat16* baseH = A1h;
        const __nv_bfloat16* baseL = A1l;
        int kl = kk;
        if (MODE == 0 && kk >= FF) { baseH = A2h; baseL = A2l; kl = kk - FF; }
        const __nv_bfloat16* gH = baseH + (size_t)(m0 + ar)*FF + kl + ak;
        const __nv_bfloat16* gL = baseL + (size_t)(m0 + ar)*FF + kl + ak;
        pa0 = *(const uint4*)gH; pa1 = *(const uint4*)(gH + 8);
        pa2 = *(const uint4*)gL; pa3 = *(const uint4*)(gL + 8);
        if (doB) {
            const __nv_bfloat16* gBh = Bh0 + (size_t)(n0 + br)*ldb + kk + bk;
            const __nv_bfloat16* gBl = Bl0 + (size_t)(n0 + br)*ldb + kk + bk;
            pb0 = *(const uint4*)gBh; pb1 = *(const uint4*)(gBh + 8);
            pb2 = *(const uint4*)gBl; pb3 = *(const uint4*)(gBl + 8);
        }
    };

    fetch(0);
    for (int kk = 0; kk < K; kk += 32) {
        *(uint4*)&sAh[ar*SKP + ak]     = pa0;
        *(uint4*)&sAh[ar*SKP + ak + 8] = pa1;
        *(uint4*)&sAl[ar*SKP + ak]     = pa2;
        *(uint4*)&sAl[ar*SKP + ak + 8] = pa3;
        if (doB) {
            *(uint4*)&sBh[br*SKP + bk]     = pb0;
            *(uint4*)&sBh[br*SKP + bk + 8] = pb1;
            *(uint4*)&sBl[br*SKP + bk]     = pb2;
            *(uint4*)&sBl[br*SKP + bk + 8] = pb3;
        }
        __syncthreads();
        if (kk + 32 < K) fetch(kk + 32);   // overlap next gmem load with MMAs

        #pragma unroll
        for (int kq = 0; kq < 32; kq += 16) {
            unsigned ah[2][4], al[2][4], bh[4][2], bl[4][2];
            #pragma unroll
            for (int i = 0; i < 2; ++i) {
                int row = wm*32 + i*16 + (lane & 15);
                int col = kq + ((lane >> 4) << 3);
                ldsm4(ah[i], &sAh[row*SKP + col]);
                ldsm4(al[i], &sAl[row*SKP + col]);
            }
            {   // B fragments via ldmatrix: 4 mats = (j, j+1) x (k0, k8)
                int g = lane >> 3, r = lane & 7;
                int nrow = wn*32 + ((g >> 1) << 3) + r;
                int kcol = kq + ((g & 1) << 3);
                unsigned t0[4], t1[4], u0[4], u1[4];
                ldsm4(t0, &sBh[(nrow)      * SKP + kcol]);
                ldsm4(t1, &sBh[(nrow + 16) * SKP + kcol]);
                ldsm4(u0, &sBl[(nrow)      * SKP + kcol]);
                ldsm4(u1, &sBl[(nrow + 16) * SKP + kcol]);
                bh[0][0]=t0[0]; bh[0][1]=t0[1]; bh[1][0]=t0[2]; bh[1][1]=t0[3];
                bh[2][0]=t1[0]; bh[2][1]=t1[1]; bh[3][0]=t1[2]; bh[3][1]=t1[3];
                bl[0][0]=u0[0]; bl[0][1]=u0[1]; bl[1][0]=u0[2]; bl[1][1]=u0[3];
                bl[2][0]=u1[0]; bl[2][1]=u1[1]; bl[3][0]=u1[2]; bl[3][1]=u1[3];
            }
            #pragma unroll
            for (int i = 0; i < 2; ++i)
                #pragma unroll
                for (int j = 0; j < 4; ++j) {
                    mma16816(acc[i][j], ah[i], bh[j]);
                    mma16816(acc[i][j], al[i], bh[j]);
                    mma16816(acc[i][j], ah[i], bl[j]);
                }
        }
        __syncthreads();
    }

    // stage accumulators to smem
    #pragma unroll
    for (int i = 0; i < 2; ++i) {
        int r = wm*32 + i*16 + (lane >> 2);
        #pragma unroll
        for (int j = 0; j < 4; ++j) {
            int cc = wn*32 + j*8 + (lane & 3)*2;
            Cs[r*72 + cc]         = acc[i][j][0];
            Cs[r*72 + cc + 1]     = acc[i][j][1];
            Cs[(r+8)*72 + cc]     = acc[i][j][2];
            Cs[(r+8)*72 + cc + 1] = acc[i][j][3];
        }
    }
    __syncthreads();

    if (MODE == 0) {
        // LSTM cell: 96 rows x 16 h-units (gate quads i,f,g,o)
        for (int idx = tid; idx < 96*16; idx += THREADS) {
            int r = idx >> 4, u = idx & 15;
            float4 gv = *(const float4*)&Cs[r*72 + u*4];
            int nb = n0 + u*4;
            float vi = sigf     (gv.x + bias[nb + 0]);
            float vf = sigf     (gv.y + bias[nb + 1]);
            float vg = tanh_fast(gv.z + bias[nb + 2]);
            float vo = sigf     (gv.w + bias[nb + 3]);
            int off = (m0 + r)*HH + (n0 >> 2) + u;
            float c = vf * Cmem[off] + vi * vg;
            Cmem[off] = c;
            Hs[r*17 + u] = vo * tanh_fast(c);
        }
        __syncthreads();
        // node-mix the fresh h (4 complete batches in this block) -> Gh bf16 hi/lo
        for (int idx = tid; idx < 96*16; idx += THREADS) {
            int r = idx >> 4, u = idx & 15;
            int lb = r / NN, n = r - lb*NN;
            float a = 0.f;
            #pragma unroll
            for (int m = 0; m < NN; ++m)
                a += sG[n*NN + m] * Hs[(lb*NN + m)*17 + u];
            __nv_bfloat16 hv = __float2bfloat16(a);
            int off = (m0 + r)*HH + (n0 >> 2) + u;
            GoH[off] = hv;
            GoL[off] = __float2bfloat16(a - __bfloat162float(hv));
        }
    } else {
        for (int idx = tid; idx < 96*64; idx += THREADS) {
            int r = idx >> 6, cc = idx & 63;
            float v = Cs[r*72 + cc] + bias[n0 + cc];
            if (MODE == 2) v = tanh_fast(v);
            OutF[(size_t)(m0 + r)*Nn + n0 + cc] = v;
        }
    }
}

// ---------------------------------------------------------------------------
extern "C" void kernel_launch(void* const* d_in, const int* in_sizes, int n_in,
                              void* d_out, int out_size)
{
    const float* x    = (const float*)d_in[0];
    const float* G    = (const float*)d_in[1];
    const float* W_ih = (const float*)d_in[2];
    const float* b_ih = (const float*)d_in[3];
    const float* W_hh = (const float*)d_in[4];
    const float* b_hh = (const float*)d_in[5];
    const float* W_h1 = (const float*)d_in[6];
    const float* b_h1 = (const float*)d_in[7];
    const float* W_h2 = (const float*)d_in[8];
    const float* b_h2 = (const float*)d_in[9];
    const float* W_fc = (const float*)d_in[10];
    const float* b_fc = (const float*)d_in[11];
    float* out = (float*)d_out;

    __nv_bfloat16 *Xh, *Xl, *Ghh, *Ghl, *Wch, *Wcl, *W1h, *W1l, *W2h, *W2l, *Wfh, *Wfl;
    float *bcat, *h, *c;
    cudaGetSymbolAddress((void**)&Xh,  g_Xh);
    cudaGetSymbolAddress((void**)&Xl,  g_Xl);
    cudaGetSymbolAddress((void**)&Ghh, g_Ghh);
    cudaGetSymbolAddress((void**)&Ghl, g_Ghl);
    cudaGetSymbolAddress((void**)&Wch, g_Wch);
    cudaGetSymbolAddress((void**)&Wcl, g_Wcl);
    cudaGetSymbolAddress((void**)&W1h, g_W1h);
    cudaGetSymbolAddress((void**)&W1l, g_W1l);
    cudaGetSymbolAddress((void**)&W2h, g_W2h);
    cudaGetSymbolAddress((void**)&W2l, g_W2l);
    cudaGetSymbolAddress((void**)&Wfh, g_Wfh);
    cudaGetSymbolAddress((void**)&Wfl, g_Wfl);
    cudaGetSymbolAddress((void**)&bcat, g_bcat);
    cudaGetSymbolAddress((void**)&h,   g_h);
    cudaGetSymbolAddress((void**)&c,   g_c);

    const size_t SMSZ = 2304 + 96*72*4 + 96*17*4;   // 36480 B (> staging 27904)

    // prep
    mix_x<<<BB*TT, 256>>>(x, G);
    pack_cat<<<(G4H*KCAT)/256, 256>>>(W_ih, W_hh, b_ih, b_hh);
    pack_w<<<(HH*FF)/256, 256>>>(W_h1, W1h, W1l);
    pack_w<<<(HH*FF)/256, 256>>>(W_h2, W2h, W2l);
    pack_w<<<(HH*HH)/256, 256>>>(W_fc, Wfh, Wfl);

    // h0 / c0
    dim3 gSm(4, 16);
    mma_gemm<1><<<gSm, THREADS, SMSZ>>>(Xh, Xl, nullptr, nullptr, W1h, W1l, b_h1,
                                        nullptr, h, nullptr, nullptr, nullptr,
                                        256, 256, 256);
    mma_gemm<1><<<gSm, THREADS, SMSZ>>>(Xh, Xl, nullptr, nullptr, W2h, W2l, b_h2,
                                        nullptr, c, nullptr, nullptr, nullptr,
                                        256, 256, 256);
    mix_h<<<BB, 256>>>(G, Ghh, Ghl);   // buffer 0

    // scan: single fused kernel per step (GEMM + cell + node-mix)
    dim3 gCell(16, 16);
    for (int t = 0; t < TT; ++t) {
        int pi = t & 1, po = 1 - pi;
        mma_gemm<0><<<gCell, THREADS, SMSZ>>>(
            Xh + (size_t)t*ROWS*FF, Xl + (size_t)t*ROWS*FF,
            Ghh + (size_t)pi*ROWS*HH, Ghl + (size_t)pi*ROWS*HH,
            Wch, Wcl, bcat, G,
            nullptr, c,
            Ghh + (size_t)po*ROWS*HH, Ghl + (size_t)po*ROWS*HH,
            KCAT, G4H, KCAT);
    }

    // output: tanh((G h) @ W_fc^T + b_fc) ; after 50 steps Gh lives in buffer 0
    mma_gemm<2><<<gSm, THREADS, SMSZ>>>(Ghh, Ghl, nullptr, nullptr, Wfh, Wfl, b_fc,
                                        nullptr, out, nullptr, nullptr, nullptr,
                                        256, 256, 256);
}

// round 5
// speedup vs baseline: 2.3558x; 1.1587x over previous
#include <cuda_runtime.h>
#include <cuda_bf16.h>
#include <math.h>
#include <stdint.h>

#define BB 64
#define TT 50
#define NN 24
#define FF 256
#define HH 256
#define G4H 1024
#define ROWS (BB*NN)   // 1536
#define KCAT 512
#define SKP 40         // padded bf16 smem row stride for staged tiles
#define TM 96
#define TN 128
#define CROW 520       // persistent B-hi cache row stride (bf16 elems)

// ------------------ device scratch (no allocations allowed) ----------------
__device__ __nv_bfloat16 g_Xh[(size_t)TT*ROWS*FF];
__device__ __nv_bfloat16 g_Xl[(size_t)TT*ROWS*FF];
__device__ __nv_bfloat16 g_Ghh[2][ROWS*HH];          // ping-pong node-mixed h
__device__ __nv_bfloat16 g_Ghl[2][ROWS*HH];
__device__ __nv_bfloat16 g_Wch[(size_t)G4H*KCAT];    // [W_ih|W_hh], gate-interleaved
__device__ __nv_bfloat16 g_Wcl[(size_t)G4H*KCAT];
__device__ __nv_bfloat16 g_W1h[HH*FF], g_W1l[HH*FF];
__device__ __nv_bfloat16 g_W2h[HH*FF], g_W2l[HH*FF];
__device__ __nv_bfloat16 g_Wfh[HH*HH], g_Wfl[HH*HH];
__device__ float g_bcat[G4H];
__device__ float g_h[ROWS*HH];
__device__ float g_c[ROWS*HH];
__device__ unsigned g_bar[16];

// ------------------ helpers ------------------------------------------------
__device__ __forceinline__ float sigf(float x) { return 1.f / (1.f + __expf(-x)); }
__device__ __forceinline__ float tanh_fast(float x) {
    float ax = fabsf(x);
    float t = __expf(-2.f * ax);
    float r = (1.f - t) / (1.f + t);
    return copysignf(r, x);
}
__device__ __forceinline__ void mma16816(float* d, const unsigned* a, const unsigned* b) {
    asm volatile("mma.sync.aligned.m16n8k16.row.col.f32.bf16.bf16.f32 "
                 "{%0,%1,%2,%3},{%4,%5,%6,%7},{%8,%9},{%0,%1,%2,%3};"
                 : "+f"(d[0]), "+f"(d[1]), "+f"(d[2]), "+f"(d[3])
                 : "r"(a[0]), "r"(a[1]), "r"(a[2]), "r"(a[3]),
                   "r"(b[0]), "r"(b[1]));
}
__device__ __forceinline__ void ldsm4(unsigned* r, const __nv_bfloat16* p) {
    unsigned addr = (unsigned)__cvta_generic_to_shared(p);
    asm volatile("ldmatrix.sync.aligned.m8n8.x4.shared.b16 {%0,%1,%2,%3},[%4];"
                 : "=r"(r[0]), "=r"(r[1]), "=r"(r[2]), "=r"(r[3]) : "r"(addr));
}

// ------------------ packing -------------------------------------------------
// packed col n = 4*j + q ; original weight row r = q*256 + j  (q: i,f,g,o)
__global__ __launch_bounds__(256)
void pack_cat(const float* __restrict__ Wih, const float* __restrict__ Whh,
              const float* __restrict__ bih, const float* __restrict__ bhh)
{
    int idx = blockIdx.x * 256 + threadIdx.x;
    int n = idx >> 9, k = idx & 511;
    int r = (n & 3) * HH + (n >> 2);
    float v = (k < 256) ? Wih[r*256 + k] : Whh[r*256 + (k - 256)];
    __nv_bfloat16 hv = __float2bfloat16(v);
    g_Wch[idx] = hv;
    g_Wcl[idx] = __float2bfloat16(v - __bfloat162float(hv));
    if (k == 0) g_bcat[n] = bih[r] + bhh[r];
}

__global__ __launch_bounds__(256)
void pack_w(const float* __restrict__ W, __nv_bfloat16* __restrict__ Wh,
            __nv_bfloat16* __restrict__ Wl)
{
    int idx = blockIdx.x * 256 + threadIdx.x;
    float v = W[idx];
    __nv_bfloat16 hv = __float2bfloat16(v);
    Wh[idx] = hv;
    Wl[idx] = __float2bfloat16(v - __bfloat162float(hv));
}

__global__ void reset_bar() { if (threadIdx.x < 16) g_bar[threadIdx.x] = 0u; }

// ------------------ node-mix kernels ----------------------------------------
__global__ __launch_bounds__(256)
void mix_x(const float* __restrict__ x, const float* __restrict__ G)
{
    __shared__ float xs[NN*FF];
    __shared__ float Gs[NN*NN];
    int bid = blockIdx.x, t = bid / BB, b = bid % BB;
    const float* xin = x + (size_t)(b*TT + t) * NN * FF;
    size_t ob = (size_t)bid * NN * FF;
    int tid = threadIdx.x;
    for (int i = tid; i < NN*FF; i += 256) xs[i] = xin[i];
    for (int i = tid; i < NN*NN; i += 256) Gs[i] = G[i];
    __syncthreads();
    for (int i = tid; i < NN*FF; i += 256) {
        int n = i >> 8, f = i & 255;
        float a = 0.f;
        #pragma unroll
        for (int m = 0; m < NN; ++m) a += Gs[n*NN + m] * xs[m*FF + f];
        __nv_bfloat16 hv = __float2bfloat16(a);
        g_Xh[ob + i] = hv;
        g_Xl[ob + i] = __float2bfloat16(a - __bfloat162float(hv));
    }
}

__global__ __launch_bounds__(256)
void mix_h(const float* __restrict__ G, __nv_bfloat16* __restrict__ oh,
           __nv_bfloat16* __restrict__ ol)
{
    __shared__ float hs[NN*HH];
    __shared__ float Gs[NN*NN];
    int b = blockIdx.x, tid = threadIdx.x;
    const float* hin = g_h + (size_t)b * NN * HH;
    size_t ob = (size_t)b * NN * HH;
    for (int i = tid; i < NN*HH; i += 256) hs[i] = hin[i];
    for (int i = tid; i < NN*NN; i += 256) Gs[i] = G[i];
    __syncthreads();
    for (int i = tid; i < NN*HH; i += 256) {
        int n = i >> 8, f = i & 255;
        float a = 0.f;
        #pragma unroll
        for (int m = 0; m < NN; ++m) a += Gs[n*NN + m] * hs[m*HH + f];
        __nv_bfloat16 hv = __float2bfloat16(a);
        oh[ob + i] = hv;
        ol[ob + i] = __float2bfloat16(a - __bfloat162float(hv));
    }
}

// ------------------ small split-precision GEMM (96x64 tile, M=1536,N=256,K=256)
template<int ACT>
__global__ __launch_bounds__(192)
void mma_small(const __nv_bfloat16* __restrict__ Ah, const __nv_bfloat16* __restrict__ Al,
               const __nv_bfloat16* __restrict__ Bh0, const __nv_bfloat16* __restrict__ Bl0,
               const float* __restrict__ bias, float* __restrict__ Out)
{
    __shared__ __align__(16) char smbuf[26624];
    __nv_bfloat16* sAh = (__nv_bfloat16*)smbuf;        // 96*SKP
    __nv_bfloat16* sAl = sAh + 96*SKP;
    __nv_bfloat16* sBh = sAl + 96*SKP;                 // 64*SKP
    __nv_bfloat16* sBl = sBh + 64*SKP;
    float* Cs = (float*)smbuf;                         // 96*68

    int tid = threadIdx.x, lane = tid & 31, warp = tid >> 5;
    int wm = warp >> 1, wn = warp & 1;
    int m0 = blockIdx.y * 96, n0 = blockIdx.x * 64;

    float acc[2][4][4] = {};
    int ar = tid >> 1, ak = (tid & 1) * 16;
    int br = tid >> 1, bk = (tid & 1) * 16;
    bool doB = tid < 128;
    uint4 pa0, pa1, pa2, pa3, pb0, pb1, pb2, pb3;

    auto fetch = [&](int kk) {
        const __nv_bfloat16* gH = Ah + (size_t)(m0 + ar)*256 + kk + ak;
        const __nv_bfloat16* gL = Al + (size_t)(m0 + ar)*256 + kk + ak;
        pa0 = *(const uint4*)gH; pa1 = *(const uint4*)(gH + 8);
        pa2 = *(const uint4*)gL; pa3 = *(const uint4*)(gL + 8);
        if (doB) {
            const __nv_bfloat16* gBh = Bh0 + (size_t)(n0 + br)*256 + kk + bk;
            const __nv_bfloat16* gBl = Bl0 + (size_t)(n0 + br)*256 + kk + bk;
            pb0 = *(const uint4*)gBh; pb1 = *(const uint4*)(gBh + 8);
            pb2 = *(const uint4*)gBl; pb3 = *(const uint4*)(gBl + 8);
        }
    };

    fetch(0);
    for (int kk = 0; kk < 256; kk += 32) {
        *(uint4*)&sAh[ar*SKP + ak]     = pa0;
        *(uint4*)&sAh[ar*SKP + ak + 8] = pa1;
        *(uint4*)&sAl[ar*SKP + ak]     = pa2;
        *(uint4*)&sAl[ar*SKP + ak + 8] = pa3;
        if (doB) {
            *(uint4*)&sBh[br*SKP + bk]     = pb0;
            *(uint4*)&sBh[br*SKP + bk + 8] = pb1;
            *(uint4*)&sBl[br*SKP + bk]     = pb2;
            *(uint4*)&sBl[br*SKP + bk + 8] = pb3;
        }
        __syncthreads();
        if (kk + 32 < 256) fetch(kk + 32);

        #pragma unroll
        for (int kq = 0; kq < 32; kq += 16) {
            unsigned ah[2][4], al[2][4], bh[4][2], bl[4][2];
            #pragma unroll
            for (int i = 0; i < 2; ++i) {
                int row = wm*32 + i*16 + (lane & 15);
                int col = kq + ((lane >> 4) << 3);
                ldsm4(ah[i], &sAh[row*SKP + col]);
                ldsm4(al[i], &sAl[row*SKP + col]);
            }
            {
                int g = lane >> 3, r = lane & 7;
                int nrow = wn*32 + ((g >> 1) << 3) + r;
                int kcol = kq + ((g & 1) << 3);
                unsigned t0[4], t1[4], u0[4], u1[4];
                ldsm4(t0, &sBh[(nrow)      * SKP + kcol]);
                ldsm4(t1, &sBh[(nrow + 16) * SKP + kcol]);
                ldsm4(u0, &sBl[(nrow)      * SKP + kcol]);
                ldsm4(u1, &sBl[(nrow + 16) * SKP + kcol]);
                bh[0][0]=t0[0]; bh[0][1]=t0[1]; bh[1][0]=t0[2]; bh[1][1]=t0[3];
                bh[2][0]=t1[0]; bh[2][1]=t1[1]; bh[3][0]=t1[2]; bh[3][1]=t1[3];
                bl[0][0]=u0[0]; bl[0][1]=u0[1]; bl[1][0]=u0[2]; bl[1][1]=u0[3];
                bl[2][0]=u1[0]; bl[2][1]=u1[1]; bl[3][0]=u1[2]; bl[3][1]=u1[3];
            }
            #pragma unroll
            for (int i = 0; i < 2; ++i)
                #pragma unroll
                for (int j = 0; j < 4; ++j) {
                    mma16816(acc[i][j], ah[i], bh[j]);
                    mma16816(acc[i][j], al[i], bh[j]);
                    mma16816(acc[i][j], ah[i], bl[j]);
                }
        }
        __syncthreads();
    }

    #pragma unroll
    for (int i = 0; i < 2; ++i) {
        int r = wm*32 + i*16 + (lane >> 2);
        #pragma unroll
        for (int j = 0; j < 4; ++j) {
            int cc = wn*32 + j*8 + (lane & 3)*2;
            Cs[r*68 + cc]         = acc[i][j][0];
            Cs[r*68 + cc + 1]     = acc[i][j][1];
            Cs[(r+8)*68 + cc]     = acc[i][j][2];
            Cs[(r+8)*68 + cc + 1] = acc[i][j][3];
        }
    }
    __syncthreads();
    for (int idx = tid; idx < 96*64; idx += 192) {
        int r = idx >> 6, cc = idx & 63;
        float v = Cs[r*68 + cc] + bias[n0 + cc];
        if (ACT) v = tanh_fast(v);
        Out[(size_t)(m0 + r)*256 + n0 + cc] = v;
    }
}

// ------------------ persistent 50-step scan kernel ---------------------------
// 128 CTAs: grp = cta>>3 owns rows m0=grp*96; nc = cta&7 owns gate cols n0=nc*128
// (= h-units u0=nc*32). B-hi cached in smem whole kernel; c held in registers.
__global__ __launch_bounds__(192, 1)
void lstm_persist(const __nv_bfloat16* __restrict__ Xh, const __nv_bfloat16* __restrict__ Xl,
                  const __nv_bfloat16* __restrict__ Wh, const __nv_bfloat16* __restrict__ Wl,
                  const float* __restrict__ bias, const float* __restrict__ Gmat,
                  const float* __restrict__ Cinit,
                  __nv_bfloat16* __restrict__ GhH, __nv_bfloat16* __restrict__ GhL)
{
    extern __shared__ __align__(16) char sm[];
    __nv_bfloat16* sBc = (__nv_bfloat16*)sm;            // 128 x CROW (133120 B)
    float* sG = (float*)(sm + 133120);                  // 2304 B
    float* Hs = (float*)(sm + 135424);                  // 96*33*4 = 12672 B
    char*  un = sm + 148096;                            // union region
    __nv_bfloat16* sAh = (__nv_bfloat16*)un;            // 96*SKP
    __nv_bfloat16* sAl = sAh + TM*SKP;
    __nv_bfloat16* sBl = sAl + TM*SKP;                  // 128*SKP
    float* Cs = (float*)un;                             // 96*132 floats

    const int tid = threadIdx.x, lane = tid & 31, warp = tid >> 5;
    const int wm = warp >> 1, wn = warp & 1;            // 3x2 warps
    const int grp = blockIdx.x >> 3, nc = blockIdx.x & 7;
    const int m0 = grp*TM, n0 = nc*TN, u0 = nc*32;

    // persistent B-hi cache (128 rows x 512 k) + G
    for (int i = tid; i < TN*64; i += 192) {            // 8192 16B-chunks
        int r = i >> 6, k = (i & 63) * 8;
        *(uint4*)&sBc[r*CROW + k] = *(const uint4*)(Wh + (size_t)(n0 + r)*KCAT + k);
    }
    for (int i = tid; i < NN*NN; i += 192) sG[i] = Gmat[i];

    float creg[16];
    #pragma unroll
    for (int k = 0; k < 16; ++k) {
        int idx = tid + k*192, r = idx >> 5, u = idx & 31;
        creg[k] = Cinit[(m0 + r)*HH + u0 + u];
    }
    __syncthreads();

    const int ar = tid >> 1, ak = (tid & 1)*16;         // A staging slots
    uint4 pa[4], pb[3];

    for (int t = 0; t < TT; ++t) {
        const int pi = t & 1, po = pi ^ 1;
        const __nv_bfloat16* A1h = Xh + (size_t)t*ROWS*FF;
        const __nv_bfloat16* A1l = Xl + (size_t)t*ROWS*FF;
        const __nv_bfloat16* A2h = GhH + (size_t)pi*ROWS*HH;
        const __nv_bfloat16* A2l = GhL + (size_t)pi*ROWS*HH;

        float acc[2][8][4];
        #pragma unroll
        for (int i = 0; i < 2; ++i)
            #pragma unroll
            for (int j = 0; j < 8; ++j)
                #pragma unroll
                for (int e = 0; e < 4; ++e) acc[i][j][e] = 0.f;

        auto fetchA = [&](const __nv_bfloat16* H, const __nv_bfloat16* L, int kl, bool cg) {
            const __nv_bfloat16* gh = H + (size_t)(m0 + ar)*256 + kl + ak;
            const __nv_bfloat16* gl = L + (size_t)(m0 + ar)*256 + kl + ak;
            if (cg) {
                pa[0] = __ldcg((const uint4*)gh); pa[1] = __ldcg((const uint4*)(gh + 8));
                pa[2] = __ldcg((const uint4*)gl); pa[3] = __ldcg((const uint4*)(gl + 8));
            } else {
                pa[0] = *(const uint4*)gh; pa[1] = *(const uint4*)(gh + 8);
                pa[2] = *(const uint4*)gl; pa[3] = *(const uint4*)(gl + 8);
            }
        };
        auto fetchB = [&](int kk) {
            #pragma unroll
            for (int s = 0; s < 3; ++s) {
                int cch = tid + s*192;
                if (cch < 512) {
                    int brr = cch >> 2, bkk = (cch & 3) * 8;
                    pb[s] = *(const uint4*)(Wl + (size_t)(n0 + brr)*KCAT + kk + bkk);
                }
            }
        };
        auto stage = [&]() {
            *(uint4*)&sAh[ar*SKP + ak]     = pa[0];
            *(uint4*)&sAh[ar*SKP + ak + 8] = pa[1];
            *(uint4*)&sAl[ar*SKP + ak]     = pa[2];
            *(uint4*)&sAl[ar*SKP + ak + 8] = pa[3];
            #pragma unroll
            for (int s = 0; s < 3; ++s) {
                int cch = tid + s*192;
                if (cch < 512) {
                    int brr = cch >> 2, bkk = (cch & 3) * 8;
                    *(uint4*)&sBl[brr*SKP + bkk] = pb[s];
                }
            }
        };
        auto compute = [&](int kk) {
            #pragma unroll
            for (int kq = 0; kq < 32; kq += 16) {
                unsigned ah[2][4], al[2][4], bh[8][2], bl[8][2];
                #pragma unroll
                for (int i = 0; i < 2; ++i) {
                    int row = wm*32 + i*16 + (lane & 15);
                    int col = kq + ((lane >> 4) << 3);
                    ldsm4(ah[i], &sAh[row*SKP + col]);
                    ldsm4(al[i], &sAl[row*SKP + col]);
                }
                #pragma unroll
                for (int jj = 0; jj < 4; ++jj) {
                    int nr = wn*64 + jj*16 + ((lane >> 4) << 3) + (lane & 7);
                    int kc = kq + (((lane >> 3) & 1) << 3);
                    unsigned th[4], tl[4];
                    ldsm4(th, &sBc[nr*CROW + kk + kc]);   // cached B-hi (global k)
                    ldsm4(tl, &sBl[nr*SKP + kc]);          // staged B-lo
                    bh[jj*2][0]=th[0]; bh[jj*2][1]=th[1];
                    bh[jj*2+1][0]=th[2]; bh[jj*2+1][1]=th[3];
                    bl[jj*2][0]=tl[0]; bl[jj*2][1]=tl[1];
                    bl[jj*2+1][0]=tl[2]; bl[jj*2+1][1]=tl[3];
                }
                #pragma unroll
                for (int i = 0; i < 2; ++i)
                    #pragma unroll
                    for (int j = 0; j < 8; ++j) {
                        mma16816(acc[i][j], ah[i], bh[j]);
                        mma16816(acc[i][j], al[i], bh[j]);
                        mma16816(acc[i][j], ah[i], bl[j]);
                    }
            }
        };

        // phase 1: k in [0,256) — A = node-mixed x(t), no peer dependency
        fetchA(A1h, A1l, 0, false); fetchB(0);
        for (int kk = 0; kk < 256; kk += 32) {
            __syncthreads();
            stage();
            __syncthreads();
            if (kk + 32 < 256) { fetchA(A1h, A1l, kk + 32, false); fetchB(kk + 32); }
            compute(kk);
        }
        // wait for all 8 peers of this m-group to publish Gh(t)
        if (t > 0) {
            if (tid == 0) {
                unsigned tgt = 8u * (unsigned)t;
                while (*(volatile unsigned*)&g_bar[grp] < tgt) __nanosleep(32);
            }
            __syncthreads();
        }
        // phase 2: k in [256,512) — A = node-mixed h (L2-coherent loads)
        fetchA(A2h, A2l, 0, true); fetchB(256);
        for (int kk = 256; kk < 512; kk += 32) {
            __syncthreads();
            stage();
            __syncthreads();
            if (kk + 32 < 512) { fetchA(A2h, A2l, kk + 32 - 256, true); fetchB(kk + 32); }
            compute(kk);
        }
        __syncthreads();

        // epilogue: acc -> Cs
        #pragma unroll
        for (int i = 0; i < 2; ++i) {
            int r = wm*32 + i*16 + (lane >> 2);
            #pragma unroll
            for (int j = 0; j < 8; ++j) {
                int cc = wn*64 + j*8 + (lane & 3)*2;
                Cs[r*132 + cc]         = acc[i][j][0];
                Cs[r*132 + cc + 1]     = acc[i][j][1];
                Cs[(r+8)*132 + cc]     = acc[i][j][2];
                Cs[(r+8)*132 + cc + 1] = acc[i][j][3];
            }
        }
        __syncthreads();
        // LSTM cell (c in registers)
        #pragma unroll
        for (int k = 0; k < 16; ++k) {
            int idx = tid + k*192, r = idx >> 5, u = idx & 31;
            float4 gv = *(const float4*)&Cs[r*132 + u*4];
            int nb = n0 + u*4;
            float vi = sigf     (gv.x + bias[nb + 0]);
            float vf = sigf     (gv.y + bias[nb + 1]);
            float vg = tanh_fast(gv.z + bias[nb + 2]);
            float vo = sigf     (gv.w + bias[nb + 3]);
            float cv = vf * creg[k] + vi * vg;
            creg[k] = cv;
            Hs[r*33 + u] = vo * tanh_fast(cv);
        }
        __syncthreads();
        // node-mix fresh h -> Gh(po), bf16 hi/lo
        #pragma unroll
        for (int k = 0; k < 16; ++k) {
            int idx = tid + k*192, r = idx >> 5, u = idx & 31;
            int lb = r / NN, n = r - lb*NN;
            float a = 0.f;
            #pragma unroll
            for (int m = 0; m < NN; ++m) a += sG[n*NN + m] * Hs[(lb*NN + m)*33 + u];
            __nv_bfloat16 hv = __float2bfloat16(a);
            int off = (m0 + r)*HH + u0 + u;
            GhH[(size_t)po*ROWS*HH + off] = hv;
            GhL[(size_t)po*ROWS*HH + off] = __float2bfloat16(a - __bfloat162float(hv));
        }
        __threadfence();
        __syncthreads();
        if (tid == 0) atomicAdd(&g_bar[grp], 1u);
    }
}

// ---------------------------------------------------------------------------
extern "C" void kernel_launch(void* const* d_in, const int* in_sizes, int n_in,
                              void* d_out, int out_size)
{
    const float* x    = (const float*)d_in[0];
    const float* G    = (const float*)d_in[1];
    const float* W_ih = (const float*)d_in[2];
    const float* b_ih = (const float*)d_in[3];
    const float* W_hh = (const float*)d_in[4];
    const float* b_hh = (const float*)d_in[5];
    const float* W_h1 = (const float*)d_in[6];
    const float* b_h1 = (const float*)d_in[7];
    const float* W_h2 = (const float*)d_in[8];
    const float* b_h2 = (const float*)d_in[9];
    const float* W_fc = (const float*)d_in[10];
    const float* b_fc = (const float*)d_in[11];
    float* out = (float*)d_out;

    __nv_bfloat16 *Xh, *Xl, *Ghh, *Ghl, *Wch, *Wcl, *W1h, *W1l, *W2h, *W2l, *Wfh, *Wfl;
    float *bcat, *h, *c;
    cudaGetSymbolAddress((void**)&Xh,  g_Xh);
    cudaGetSymbolAddress((void**)&Xl,  g_Xl);
    cudaGetSymbolAddress((void**)&Ghh, g_Ghh);
    cudaGetSymbolAddress((void**)&Ghl, g_Ghl);
    cudaGetSymbolAddress((void**)&Wch, g_Wch);
    cudaGetSymbolAddress((void**)&Wcl, g_Wcl);
    cudaGetSymbolAddress((void**)&W1h, g_W1h);
    cudaGetSymbolAddress((void**)&W1l, g_W1l);
    cudaGetSymbolAddress((void**)&W2h, g_W2h);
    cudaGetSymbolAddress((void**)&W2l, g_W2l);
    cudaGetSymbolAddress((void**)&Wfh, g_Wfh);
    cudaGetSymbolAddress((void**)&Wfl, g_Wfl);
    cudaGetSymbolAddress((void**)&bcat, g_bcat);
    cudaGetSymbolAddress((void**)&h,   g_h);
    cudaGetSymbolAddress((void**)&c,   g_c);

    const size_t SMP = 198784;   // persistent kernel dynamic smem
    cudaFuncSetAttribute(lstm_persist, cudaFuncAttributeMaxDynamicSharedMemorySize, (int)SMP);

    // prep
    mix_x<<<BB*TT, 256>>>(x, G);
    pack_cat<<<(G4H*KCAT)/256, 256>>>(W_ih, W_hh, b_ih, b_hh);
    pack_w<<<(HH*FF)/256, 256>>>(W_h1, W1h, W1l);
    pack_w<<<(HH*FF)/256, 256>>>(W_h2, W2h, W2l);
    pack_w<<<(HH*HH)/256, 256>>>(W_fc, Wfh, Wfl);
    reset_bar<<<1, 32>>>();

    // h0 / c0 from t=0 slice of node-mixed x
    dim3 gSm(4, 16);
    mma_small<0><<<gSm, 192>>>(Xh, Xl, W1h, W1l, b_h1, h);
    mma_small<0><<<gSm, 192>>>(Xh, Xl, W2h, W2l, b_h2, c);
    mix_h<<<BB, 256>>>(G, Ghh, Ghl);   // Gh(0) into buffer 0

    // persistent 50-step scan
    lstm_persist<<<128, 192, SMP>>>(Xh, Xl, Wch, Wcl, bcat, G, c, Ghh, Ghl);

    // output: tanh((G h) @ W_fc^T + b_fc); after 50 steps Gh is in buffer 0
    mma_small<1><<<gSm, 192>>>(Ghh, Ghl, Wfh, Wfl, b_fc, out);
}

// round 7
// speedup vs baseline: 3.8371x; 1.6288x over previous
#include <cuda_runtime.h>
#include <cuda_fp16.h>
#include <math.h>
#include <stdint.h>

#define BB 64
#define TT 50
#define NN 24
#define FF 256
#define HH 256
#define G4H 1024
#define ROWS 1536
#define KCAT 512
#define SKP 40       // mma_small staging stride
#define WSTR 520     // persistent Wh cache row stride (fp16 elems) — conflict-free
#define ASTR 72      // persistent act staging row stride (fp16 elems) — conflict-free

// ---- persistent smem layout (bytes) ----
#define SM_WH    0                       // 128*WSTR*2 = 133120
#define SM_G     133120                  // 2304
#define SM_BIAS  135424                  // 512
#define SM_HS    135936                  // 96*33*4 = 12672
#define SM_UNION 148608                  // max(staging 27648, Cs 50688)
#define OFF_BH   0
#define OFF_BL   13824                   // 96*ASTR*2
#define SM_TOTAL (SM_UNION + 50688)      // 199296 B

// ------------------ device scratch ------------------------------------------
__device__ __half g_Xh[(size_t)TT*ROWS*FF];
__device__ __half g_Xl[(size_t)TT*ROWS*FF];
__device__ __half g_Ghh[2][ROWS*HH];
__device__ __half g_Ghl[2][ROWS*HH];
__device__ __half g_Wch[(size_t)G4H*KCAT];   // [W_ih|W_hh] gate-interleaved, fp16 hi
__device__ __half g_W1h[HH*FF], g_W1l[HH*FF];
__device__ __half g_W2h[HH*FF], g_W2l[HH*FF];
__device__ __half g_Wfh[HH*HH], g_Wfl[HH*HH];
__device__ float g_bcat[G4H];
__device__ float g_h[ROWS*HH];
__device__ float g_c[ROWS*HH];
__device__ unsigned g_bar[16];

// ------------------ helpers --------------------------------------------------
__device__ __forceinline__ float sigf(float x) { return 1.f / (1.f + __expf(-x)); }
__device__ __forceinline__ float tanh_fast(float x) {
    float ax = fabsf(x);
    float t = __expf(-2.f * ax);
    return copysignf((1.f - t) / (1.f + t), x);
}
__device__ __forceinline__ void mma16816(float* d, const unsigned* a, const unsigned* b) {
    asm volatile("mma.sync.aligned.m16n8k16.row.col.f32.f16.f16.f32 "
                 "{%0,%1,%2,%3},{%4,%5,%6,%7},{%8,%9},{%0,%1,%2,%3};"
                 : "+f"(d[0]), "+f"(d[1]), "+f"(d[2]), "+f"(d[3])
                 : "r"(a[0]), "r"(a[1]), "r"(a[2]), "r"(a[3]), "r"(b[0]), "r"(b[1]));
}
__device__ __forceinline__ void ldsm4(unsigned* r, const __half* p) {
    unsigned addr = (unsigned)__cvta_generic_to_shared(p);
    asm volatile("ldmatrix.sync.aligned.m8n8.x4.shared.b16 {%0,%1,%2,%3},[%4];"
                 : "=r"(r[0]), "=r"(r[1]), "=r"(r[2]), "=r"(r[3]) : "r"(addr));
}

// ------------------ packing ---------------------------------------------------
// packed col n = 4*j + q ; original weight row r = q*256 + j  (q: i,f,g,o)
__global__ __launch_bounds__(256)
void pack_cat(const float* __restrict__ Wih, const float* __restrict__ Whh,
              const float* __restrict__ bih, const float* __restrict__ bhh)
{
    int idx = blockIdx.x * 256 + threadIdx.x;
    int n = idx >> 9, k = idx & 511;
    int r = (n & 3) * HH + (n >> 2);
    float v = (k < 256) ? Wih[r*256 + k] : Whh[r*256 + (k - 256)];
    g_Wch[idx] = __float2half_rn(v);
    if (k == 0) g_bcat[n] = bih[r] + bhh[r];
}
__global__ __launch_bounds__(256)
void pack_w(const float* __restrict__ W, __half* __restrict__ Wh,
            __half* __restrict__ Wl)
{
    int idx = blockIdx.x * 256 + threadIdx.x;
    float v = W[idx];
    __half hv = __float2half_rn(v);
    Wh[idx] = hv;
    Wl[idx] = __float2half_rn(v - __half2float(hv));
}
__global__ void reset_bar() { if (threadIdx.x < 16) g_bar[threadIdx.x] = 0u; }

// ------------------ node-mix ---------------------------------------------------
__global__ __launch_bounds__(256)
void mix_x(const float* __restrict__ x, const float* __restrict__ G)
{
    __shared__ float xs[NN*FF];
    __shared__ float Gs[NN*NN];
    int bid = blockIdx.x, t = bid / BB, b = bid % BB;
    const float* xin = x + (size_t)(b*TT + t) * NN * FF;
    size_t ob = (size_t)bid * NN * FF;
    int tid = threadIdx.x;
    for (int i = tid; i < NN*FF; i += 256) xs[i] = xin[i];
    for (int i = tid; i < NN*NN; i += 256) Gs[i] = G[i];
    __syncthreads();
    for (int i = tid; i < NN*FF; i += 256) {
        int n = i >> 8, f = i & 255;
        float a = 0.f;
        #pragma unroll
        for (int m = 0; m < NN; ++m) a += Gs[n*NN + m] * xs[m*FF + f];
        __half hv = __float2half_rn(a);
        g_Xh[ob + i] = hv;
        g_Xl[ob + i] = __float2half_rn(a - __half2float(hv));
    }
}
__global__ __launch_bounds__(256)
void mix_h(const float* __restrict__ G, __half* __restrict__ oh,
           __half* __restrict__ ol)
{
    __shared__ float hs[NN*HH];
    __shared__ float Gs[NN*NN];
    int b = blockIdx.x, tid = threadIdx.x;
    const float* hin = g_h + (size_t)b * NN * HH;
    size_t ob = (size_t)b * NN * HH;
    for (int i = tid; i < NN*HH; i += 256) hs[i] = hin[i];
    for (int i = tid; i < NN*NN; i += 256) Gs[i] = G[i];
    __syncthreads();
    for (int i = tid; i < NN*HH; i += 256) {
        int n = i >> 8, f = i & 255;
        float a = 0.f;
        #pragma unroll
        for (int m = 0; m < NN; ++m) a += Gs[n*NN + m] * hs[m*HH + f];
        __half hv = __float2half_rn(a);
        oh[ob + i] = hv;
        ol[ob + i] = __float2half_rn(a - __half2float(hv));
    }
}

// ------------------ small GEMM (h0/c0/final), fp16 3-term ----------------------
template<int ACT>
__global__ __launch_bounds__(192)
void mma_small(const __half* __restrict__ Ah, const __half* __restrict__ Al,
               const __half* __restrict__ Bh0, const __half* __restrict__ Bl0,
               const float* __restrict__ bias, float* __restrict__ Out)
{
    __shared__ __align__(16) char smbuf[26624];
    __half* sAh = (__half*)smbuf;
    __half* sAl = sAh + 96*SKP;
    __half* sBh = sAl + 96*SKP;
    __half* sBl = sBh + 64*SKP;
    float* Cs = (float*)smbuf;

    int tid = threadIdx.x, lane = tid & 31, warp = tid >> 5;
    int wm = warp >> 1, wn = warp & 1;
    int m0 = blockIdx.y * 96, n0 = blockIdx.x * 64;

    float acc[2][4][4] = {};
    int ar = tid >> 1, ak = (tid & 1) * 16;
    int br = tid >> 1, bk = (tid & 1) * 16;
    bool doB = tid < 128;
    uint4 pa0, pa1, pa2, pa3, pb0, pb1, pb2, pb3;

    auto fetch = [&](int kk) {
        const __half* gH = Ah + (size_t)(m0 + ar)*256 + kk + ak;
        const __half* gL = Al + (size_t)(m0 + ar)*256 + kk + ak;
        pa0 = *(const uint4*)gH; pa1 = *(const uint4*)(gH + 8);
        pa2 = *(const uint4*)gL; pa3 = *(const uint4*)(gL + 8);
        if (doB) {
            const __half* gBh = Bh0 + (size_t)(n0 + br)*256 + kk + bk;
            const __half* gBl = Bl0 + (size_t)(n0 + br)*256 + kk + bk;
            pb0 = *(const uint4*)gBh; pb1 = *(const uint4*)(gBh + 8);
            pb2 = *(const uint4*)gBl; pb3 = *(const uint4*)(gBl + 8);
        }
    };
    fetch(0);
    for (int kk = 0; kk < 256; kk += 32) {
        *(uint4*)&sAh[ar*SKP + ak]     = pa0;
        *(uint4*)&sAh[ar*SKP + ak + 8] = pa1;
        *(uint4*)&sAl[ar*SKP + ak]     = pa2;
        *(uint4*)&sAl[ar*SKP + ak + 8] = pa3;
        if (doB) {
            *(uint4*)&sBh[br*SKP + bk]     = pb0;
            *(uint4*)&sBh[br*SKP + bk + 8] = pb1;
            *(uint4*)&sBl[br*SKP + bk]     = pb2;
            *(uint4*)&sBl[br*SKP + bk + 8] = pb3;
        }
        __syncthreads();
        if (kk + 32 < 256) fetch(kk + 32);
        #pragma unroll
        for (int kq = 0; kq < 32; kq += 16) {
            unsigned ah[2][4], al[2][4], bh[4][2], bl[4][2];
            #pragma unroll
            for (int i = 0; i < 2; ++i) {
                int row = wm*32 + i*16 + (lane & 15);
                int col = kq + ((lane >> 4) << 3);
                ldsm4(ah[i], &sAh[row*SKP + col]);
                ldsm4(al[i], &sAl[row*SKP + col]);
            }
            {
                int g = lane >> 3, r = lane & 7;
                int nrow = wn*32 + ((g >> 1) << 3) + r;
                int kcol = kq + ((g & 1) << 3);
                unsigned t0[4], t1[4], u0[4], u1[4];
                ldsm4(t0, &sBh[(nrow)      * SKP + kcol]);
                ldsm4(t1, &sBh[(nrow + 16) * SKP + kcol]);
                ldsm4(u0, &sBl[(nrow)      * SKP + kcol]);
                ldsm4(u1, &sBl[(nrow + 16) * SKP + kcol]);
                bh[0][0]=t0[0]; bh[0][1]=t0[1]; bh[1][0]=t0[2]; bh[1][1]=t0[3];
                bh[2][0]=t1[0]; bh[2][1]=t1[1]; bh[3][0]=t1[2]; bh[3][1]=t1[3];
                bl[0][0]=u0[0]; bl[0][1]=u0[1]; bl[1][0]=u0[2]; bl[1][1]=u0[3];
                bl[2][0]=u1[0]; bl[2][1]=u1[1]; bl[3][0]=u1[2]; bl[3][1]=u1[3];
            }
            #pragma unroll
            for (int i = 0; i < 2; ++i)
                #pragma unroll
                for (int j = 0; j < 4; ++j) {
                    mma16816(acc[i][j], ah[i], bh[j]);
                    mma16816(acc[i][j], al[i], bh[j]);
                    mma16816(acc[i][j], ah[i], bl[j]);
                }
        }
        __syncthreads();
    }
    #pragma unroll
    for (int i = 0; i < 2; ++i) {
        int r = wm*32 + i*16 + (lane >> 2);
        #pragma unroll
        for (int j = 0; j < 4; ++j) {
            int cc = wn*32 + j*8 + (lane & 3)*2;
            Cs[r*68 + cc]         = acc[i][j][0];
            Cs[r*68 + cc + 1]     = acc[i][j][1];
            Cs[(r+8)*68 + cc]     = acc[i][j][2];
            Cs[(r+8)*68 + cc + 1] = acc[i][j][3];
        }
    }
    __syncthreads();
    for (int idx = tid; idx < 96*64; idx += 192) {
        int r = idx >> 6, cc = idx & 63;
        float v = Cs[r*68 + cc] + bias[n0 + cc];
        if (ACT) v = tanh_fast(v);
        Out[(size_t)(m0 + r)*256 + n0 + cc] = v;
    }
}

// ------------------ persistent fp16 2-term scan --------------------------------
// 128 CTAs: grp = cta>>3 rows m0=grp*96 (4 batches); nc = cta&7 gates n0=nc*128
// (units u0=nc*32). Warp grid 2(rows:48)x4(gates:32). Wh cached in smem.
// gates[r][g] = sum_k act[r][k]*Wh[g][k], act = hi + lo (fp16 pair).
__global__ __launch_bounds__(256, 1)
void lstm_persist(const __half* __restrict__ Xh, const __half* __restrict__ Xl,
                  const __half* __restrict__ Wh,
                  const float* __restrict__ bias, const float* __restrict__ Gmat,
                  const float* __restrict__ Cinit,
                  __half* __restrict__ GhH, __half* __restrict__ GhL)
{
    extern __shared__ __align__(16) char sm[];
    __half* sWh  = (__half*)(sm + SM_WH);
    float* sG    = (float*)(sm + SM_G);
    float* sBias = (float*)(sm + SM_BIAS);
    float* Hs    = (float*)(sm + SM_HS);
    __half* sBh  = (__half*)(sm + SM_UNION + OFF_BH);
    __half* sBl  = (__half*)(sm + SM_UNION + OFF_BL);
    float* Cs    = (float*)(sm + SM_UNION);

    const int tid = threadIdx.x, lane = tid & 31, warp = tid >> 5;
    const int wr = warp >> 2, wg = warp & 3;
    const int grp = blockIdx.x >> 3, nc = blockIdx.x & 7;
    const int m0 = grp*96, n0 = nc*128, u0 = nc*32;

    // one-time: Wh cache (128 gates x 512 k), G, bias, c
    #pragma unroll
    for (int s = 0; s < 32; ++s) {
        int e = tid + s*256;
        int r = e >> 6, kq = (e & 63) * 8;
        *(uint4*)&sWh[r*WSTR + kq] = *(const uint4*)(Wh + (size_t)(n0 + r)*KCAT + kq);
    }
    for (int i = tid; i < NN*NN; i += 256) sG[i] = Gmat[i];
    if (tid < 128) sBias[tid] = bias[n0 + tid];
    float creg[12];
    #pragma unroll
    for (int k = 0; k < 12; ++k) {
        int idx = tid + k*256, r = idx >> 5, u = idx & 31;
        creg[k] = Cinit[(m0 + r)*HH + u0 + u];
    }
    __syncthreads();

    const int ar = tid >> 3, ak = (tid & 7) * 8;   // staging: rows 0..31(+32s), k slots
    uint4 ph[3], pl[3];

    for (int t = 0; t < TT; ++t) {
        const int pi = t & 1, po = pi ^ 1;
        const __half* XhT = Xh + (size_t)t*ROWS*FF;
        const __half* XlT = Xl + (size_t)t*ROWS*FF;
        const __half* GhHp = GhH + (size_t)pi*ROWS*HH;
        const __half* GhLp = GhL + (size_t)pi*ROWS*HH;

        float acc[3][4][4];
        #pragma unroll
        for (int i = 0; i < 3; ++i)
            #pragma unroll
            for (int j = 0; j < 4; ++j)
                #pragma unroll
                for (int e = 0; e < 4; ++e) acc[i][j][e] = 0.f;

        auto fetch = [&](const __half* H, const __half* L, int kl, bool cg) {
            #pragma unroll
            for (int s = 0; s < 3; ++s) {
                const uint4* pH = (const uint4*)(H + (size_t)(m0 + ar + s*32)*256 + kl + ak);
                const uint4* pL = (const uint4*)(L + (size_t)(m0 + ar + s*32)*256 + kl + ak);
                if (cg) { ph[s] = __ldcg(pH); pl[s] = __ldcg(pL); }
                else    { ph[s] = *pH;        pl[s] = *pL;        }
            }
        };
        auto stage = [&]() {
            #pragma unroll
            for (int s = 0; s < 3; ++s) {
                *(uint4*)&sBh[(ar + s*32)*ASTR + ak] = ph[s];
                *(uint4*)&sBl[(ar + s*32)*ASTR + ak] = pl[s];
            }
        };
        auto compute = [&](int kk) {
            #pragma unroll
            for (int kq = 0; kq < 64; kq += 16) {
                unsigned ah[3][4], al[3][4], w[4][2];
                #pragma unroll
                for (int i = 0; i < 3; ++i) {
                    int row = wr*48 + i*16 + (lane & 15);
                    int col = kq + ((lane >> 4) << 3);
                    ldsm4(ah[i], &sBh[row*ASTR + col]);
                    ldsm4(al[i], &sBl[row*ASTR + col]);
                }
                #pragma unroll
                for (int j2 = 0; j2 < 2; ++j2) {
                    int g = lane >> 3, r = lane & 7;
                    int grow = wg*32 + j2*16 + ((g >> 1) << 3) + r;
                    int kcol = kk + kq + ((g & 1) << 3);
                    unsigned tw[4];
                    ldsm4(tw, &sWh[grow*WSTR + kcol]);
                    w[j2*2][0]   = tw[0]; w[j2*2][1]   = tw[1];
                    w[j2*2+1][0] = tw[2]; w[j2*2+1][1] = tw[3];
                }
                #pragma unroll
                for (int i = 0; i < 3; ++i)
                    #pragma unroll
                    for (int j = 0; j < 4; ++j) {
                        mma16816(acc[i][j], ah[i], w[j]);
                        mma16816(acc[i][j], al[i], w[j]);
                    }
            }
        };

        // phase 1: k [0,256) from x(t)
        fetch(XhT, XlT, 0, false);
        #pragma unroll
        for (int c = 0; c < 4; ++c) {
            __syncthreads();
            stage();
            __syncthreads();
            if (c < 3) fetch(XhT, XlT, (c + 1)*64, false);
            compute(c*64);
        }
        // dependency barrier: peers of this row-group must have published Gh(t)
        if (t > 0) {
            if (tid == 0) {
                unsigned tgt = 8u * (unsigned)t;
                while (*(volatile unsigned*)&g_bar[grp] < tgt) __nanosleep(32);
            }
            __syncthreads();
        }
        // phase 2: k [256,512) from Gh(t)
        fetch(GhHp, GhLp, 0, true);
        #pragma unroll
        for (int c = 4; c < 8; ++c) {
            __syncthreads();
            stage();
            __syncthreads();
            if (c < 7) fetch(GhHp, GhLp, (c - 3)*64, true);
            compute(c*64);
        }
        __syncthreads();

        // epilogue: acc -> Cs [row r][gate]
        #pragma unroll
        for (int i = 0; i < 3; ++i) {
            int r = wr*48 + i*16 + (lane >> 2);
            #pragma unroll
            for (int j = 0; j < 4; ++j) {
                int cc = wg*32 + j*8 + (lane & 3)*2;
                Cs[r*132 + cc]         = acc[i][j][0];
                Cs[r*132 + cc + 1]     = acc[i][j][1];
                Cs[(r+8)*132 + cc]     = acc[i][j][2];
                Cs[(r+8)*132 + cc + 1] = acc[i][j][3];
            }
        }
        __syncthreads();
        // LSTM cell (c in registers)
        #pragma unroll
        for (int k = 0; k < 12; ++k) {
            int idx = tid + k*256, r = idx >> 5, u = idx & 31;
            float4 gv = *(const float4*)&Cs[r*132 + 4*u];
            float4 bv = *(const float4*)&sBias[4*u];
            float vi = sigf(gv.x + bv.x);
            float vf = sigf(gv.y + bv.y);
            float vg = tanh_fast(gv.z + bv.z);
            float vo = sigf(gv.w + bv.w);
            float cv = vf * creg[k] + vi * vg;
            creg[k] = cv;
            Hs[r*33 + u] = vo * tanh_fast(cv);
        }
        __syncthreads();
        // node-mix fresh h -> Gh(po) fp16 hi/lo
        #pragma unroll
        for (int k = 0; k < 12; ++k) {
            int idx = tid + k*256, r = idx >> 5, u = idx & 31;
            int lb = r / NN, n = r - lb*NN;
            float a = 0.f;
            #pragma unroll
            for (int m = 0; m < NN; ++m) a += sG[n*NN + m] * Hs[(lb*NN + m)*33 + u];
            __half hv = __float2half_rn(a);
            size_t off = (size_t)(m0 + r)*HH + u0 + u;
            GhH[(size_t)po*ROWS*HH + off] = hv;
            GhL[(size_t)po*ROWS*HH + off] = __float2half_rn(a - __half2float(hv));
        }
        __threadfence();
        __syncthreads();
        if (tid == 0) atomicAdd(&g_bar[grp], 1u);
    }
}

// ---------------------------------------------------------------------------
extern "C" void kernel_launch(void* const* d_in, const int* in_sizes, int n_in,
                              void* d_out, int out_size)
{
    const float* x    = (const float*)d_in[0];
    const float* G    = (const float*)d_in[1];
    const float* W_ih = (const float*)d_in[2];
    const float* b_ih = (const float*)d_in[3];
    const float* W_hh = (const float*)d_in[4];
    const float* b_hh = (const float*)d_in[5];
    const float* W_h1 = (const float*)d_in[6];
    const float* b_h1 = (const float*)d_in[7];
    const float* W_h2 = (const float*)d_in[8];
    const float* b_h2 = (const float*)d_in[9];
    const float* W_fc = (const float*)d_in[10];
    const float* b_fc = (const float*)d_in[11];
    float* out = (float*)d_out;

    __half *Xh, *Xl, *Ghh, *Ghl, *Wch, *W1h, *W1l, *W2h, *W2l, *Wfh, *Wfl;
    float *bcat, *h, *c;
    cudaGetSymbolAddress((void**)&Xh,  g_Xh);
    cudaGetSymbolAddress((void**)&Xl,  g_Xl);
    cudaGetSymbolAddress((void**)&Ghh, g_Ghh);
    cudaGetSymbolAddress((void**)&Ghl, g_Ghl);
    cudaGetSymbolAddress((void**)&Wch, g_Wch);
    cudaGetSymbolAddress((void**)&W1h, g_W1h);
    cudaGetSymbolAddress((void**)&W1l, g_W1l);
    cudaGetSymbolAddress((void**)&W2h, g_W2h);
    cudaGetSymbolAddress((void**)&W2l, g_W2l);
    cudaGetSymbolAddress((void**)&Wfh, g_Wfh);
    cudaGetSymbolAddress((void**)&Wfl, g_Wfl);
    cudaGetSymbolAddress((void**)&bcat, g_bcat);
    cudaGetSymbolAddress((void**)&h,   g_h);
    cudaGetSymbolAddress((void**)&c,   g_c);

    cudaFuncSetAttribute(lstm_persist, cudaFuncAttributeMaxDynamicSharedMemorySize, SM_TOTAL);

    // prep
    mix_x<<<BB*TT, 256>>>(x, G);
    pack_cat<<<(G4H*KCAT)/256, 256>>>(W_ih, W_hh, b_ih, b_hh);
    pack_w<<<(HH*FF)/256, 256>>>(W_h1, W1h, W1l);
    pack_w<<<(HH*FF)/256, 256>>>(W_h2, W2h, W2l);
    pack_w<<<(HH*HH)/256, 256>>>(W_fc, Wfh, Wfl);
    reset_bar<<<1, 32>>>();

    // h0 / c0 from t=0 slice of node-mixed x
    dim3 gSm(4, 16);
    mma_small<0><<<gSm, 192>>>(Xh, Xl, W1h, W1l, b_h1, h);
    mma_small<0><<<gSm, 192>>>(Xh, Xl, W2h, W2l, b_h2, c);
    mix_h<<<BB, 256>>>(G, Ghh, Ghl);   // Gh(0) -> buffer 0

    // persistent fp16 2-term scan (50 steps)
    lstm_persist<<<128, 256, SM_TOTAL>>>(Xh, Xl, Wch, bcat, G, c, Ghh, Ghl);

    // output: tanh((G h) @ W_fc^T + b_fc); after 50 steps Gh is in buffer 0
    mma_small<1><<<gSm, 192>>>(Ghh, Ghl, Wfh, Wfl, b_fc, out);
}

// round 8
// speedup vs baseline: 5.5584x; 1.4486x over previous
#include <cuda_runtime.h>
#include <cuda_fp16.h>
#include <math.h>
#include <stdint.h>

#define BB 64
#define TT 50
#define NN 24
#define FF 256
#define HH 256
#define G4H 1024
#define ROWS 1536
#define KCAT 512
#define SKP 40       // mma_small staging stride
#define WSTR 520     // persistent Wh cache row stride (fp16) — conflict-free
#define ASTR 72      // act staging row stride (fp16) — conflict-free
#define PTHREADS 384

// ---- persistent smem layout (bytes) ----
#define SM_WH    0                       // 128*WSTR*2 = 133120
#define SM_G     133120                  // 2304
#define SM_BIAS  135424                  // 512
#define SM_HS    135936                  // 96*33*4 = 12672
#define SM_UNION 148608                  // staging 2*13824=27648  |  Cs 96*132*4=50688
#define BUFB     13824
#define SM_TOTAL (SM_UNION + 50688)      // 199296 B

// ------------------ device scratch ------------------------------------------
__device__ __half g_Xh[(size_t)TT*ROWS*FF];
__device__ __half g_Xl[ROWS*FF];             // t=0 slice only (h0/c0 precision)
__device__ __half g_Ghh[2][ROWS*HH];
__device__ __half g_Ghl[ROWS*HH];            // written at t=TT-1 only
__device__ __half g_Wch[(size_t)G4H*KCAT];   // [W_ih|W_hh] gate-interleaved fp16
__device__ __half g_W1h[HH*FF], g_W1l[HH*FF];
__device__ __half g_W2h[HH*FF], g_W2l[HH*FF];
__device__ __half g_Wfh[HH*HH], g_Wfl[HH*HH];
__device__ float g_bcat[G4H];
__device__ float g_h[ROWS*HH];
__device__ float g_c[ROWS*HH];
__device__ unsigned g_bar[16];

// ------------------ helpers --------------------------------------------------
__device__ __forceinline__ float sigf(float x) { return 1.f / (1.f + __expf(-x)); }
__device__ __forceinline__ float tanh_fast(float x) {
    float ax = fabsf(x);
    float t = __expf(-2.f * ax);
    return copysignf((1.f - t) / (1.f + t), x);
}
__device__ __forceinline__ void mma16816(float* d, const unsigned* a, const unsigned* b) {
    asm volatile("mma.sync.aligned.m16n8k16.row.col.f32.f16.f16.f32 "
                 "{%0,%1,%2,%3},{%4,%5,%6,%7},{%8,%9},{%0,%1,%2,%3};"
                 : "+f"(d[0]), "+f"(d[1]), "+f"(d[2]), "+f"(d[3])
                 : "r"(a[0]), "r"(a[1]), "r"(a[2]), "r"(a[3]), "r"(b[0]), "r"(b[1]));
}
__device__ __forceinline__ void ldsm4(unsigned* r, const __half* p) {
    unsigned addr = (unsigned)__cvta_generic_to_shared(p);
    asm volatile("ldmatrix.sync.aligned.m8n8.x4.shared.b16 {%0,%1,%2,%3},[%4];"
                 : "=r"(r[0]), "=r"(r[1]), "=r"(r[2]), "=r"(r[3]) : "r"(addr));
}
__device__ __forceinline__ void cp16(uint32_t s, const void* g) {
    asm volatile("cp.async.cg.shared.global [%0], [%1], 16;" :: "r"(s), "l"(g));
}

// ------------------ packing ---------------------------------------------------
// packed col n = 4*j + q ; original weight row r = q*256 + j  (q: i,f,g,o)
__global__ __launch_bounds__(256)
void pack_cat(const float* __restrict__ Wih, const float* __restrict__ Whh,
              const float* __restrict__ bih, const float* __restrict__ bhh)
{
    int idx = blockIdx.x * 256 + threadIdx.x;
    int n = idx >> 9, k = idx & 511;
    int r = (n & 3) * HH + (n >> 2);
    float v = (k < 256) ? Wih[r*256 + k] : Whh[r*256 + (k - 256)];
    g_Wch[idx] = __float2half_rn(v);
    if (k == 0) g_bcat[n] = bih[r] + bhh[r];
}
__global__ __launch_bounds__(256)
void pack_w(const float* __restrict__ W, __half* __restrict__ Wh,
            __half* __restrict__ Wl)
{
    int idx = blockIdx.x * 256 + threadIdx.x;
    float v = W[idx];
    __half hv = __float2half_rn(v);
    Wh[idx] = hv;
    Wl[idx] = __float2half_rn(v - __half2float(hv));
}
__global__ void reset_bar() { if (threadIdx.x < 16) g_bar[threadIdx.x] = 0u; }

// ------------------ node-mix ---------------------------------------------------
__global__ __launch_bounds__(256)
void mix_x(const float* __restrict__ x, const float* __restrict__ G)
{
    __shared__ float xs[NN*FF];
    __shared__ float Gs[NN*NN];
    int bid = blockIdx.x, t = bid / BB, b = bid % BB;
    const float* xin = x + (size_t)(b*TT + t) * NN * FF;
    size_t ob = (size_t)bid * NN * FF;
    int tid = threadIdx.x;
    for (int i = tid; i < NN*FF; i += 256) xs[i] = xin[i];
    for (int i = tid; i < NN*NN; i += 256) Gs[i] = G[i];
    __syncthreads();
    for (int i = tid; i < NN*FF; i += 256) {
        int n = i >> 8, f = i & 255;
        float a = 0.f;
        #pragma unroll
        for (int m = 0; m < NN; ++m) a += Gs[n*NN + m] * xs[m*FF + f];
        __half hv = __float2half_rn(a);
        g_Xh[ob + i] = hv;
        if (bid < BB)   // t==0 slice keeps a lo residual for h0/c0 precision
            g_Xl[ob + i] = __float2half_rn(a - __half2float(hv));
    }
}
__global__ __launch_bounds__(256)
void mix_h(const float* __restrict__ G, __half* __restrict__ oh)
{
    __shared__ float hs[NN*HH];
    __shared__ float Gs[NN*NN];
    int b = blockIdx.x, tid = threadIdx.x;
    const float* hin = g_h + (size_t)b * NN * HH;
    size_t ob = (size_t)b * NN * HH;
    for (int i = tid; i < NN*HH; i += 256) hs[i] = hin[i];
    for (int i = tid; i < NN*NN; i += 256) Gs[i] = G[i];
    __syncthreads();
    for (int i = tid; i < NN*HH; i += 256) {
        int n = i >> 8, f = i & 255;
        float a = 0.f;
        #pragma unroll
        for (int m = 0; m < NN; ++m) a += Gs[n*NN + m] * hs[m*HH + f];
        oh[ob + i] = __float2half_rn(a);
    }
}

// ------------------ small GEMM (h0/c0/final), fp16 3-term ----------------------
template<int ACT>
__global__ __launch_bounds__(192)
void mma_small(const __half* __restrict__ Ah, const __half* __restrict__ Al,
               const __half* __restrict__ Bh0, const __half* __restrict__ Bl0,
               const float* __restrict__ bias, float* __restrict__ Out)
{
    __shared__ __align__(16) char smbuf[26624];
    __half* sAh = (__half*)smbuf;
    __half* sAl = sAh + 96*SKP;
    __half* sBh = sAl + 96*SKP;
    __half* sBl = sBh + 64*SKP;
    float* Cs = (float*)smbuf;

    int tid = threadIdx.x, lane = tid & 31, warp = tid >> 5;
    int wm = warp >> 1, wn = warp & 1;
    int m0 = blockIdx.y * 96, n0 = blockIdx.x * 64;

    float acc[2][4][4] = {};
    int ar = tid >> 1, ak = (tid & 1) * 16;
    int br = tid >> 1, bk = (tid & 1) * 16;
    bool doB = tid < 128;
    uint4 pa0, pa1, pa2, pa3, pb0, pb1, pb2, pb3;

    auto fetch = [&](int kk) {
        const __half* gH = Ah + (size_t)(m0 + ar)*256 + kk + ak;
        const __half* gL = Al + (size_t)(m0 + ar)*256 + kk + ak;
        pa0 = *(const uint4*)gH; pa1 = *(const uint4*)(gH + 8);
        pa2 = *(const uint4*)gL; pa3 = *(const uint4*)(gL + 8);
        if (doB) {
            const __half* gBh = Bh0 + (size_t)(n0 + br)*256 + kk + bk;
            const __half* gBl = Bl0 + (size_t)(n0 + br)*256 + kk + bk;
            pb0 = *(const uint4*)gBh; pb1 = *(const uint4*)(gBh + 8);
            pb2 = *(const uint4*)gBl; pb3 = *(const uint4*)(gBl + 8);
        }
    };
    fetch(0);
    for (int kk = 0; kk < 256; kk += 32) {
        *(uint4*)&sAh[ar*SKP + ak]     = pa0;
        *(uint4*)&sAh[ar*SKP + ak + 8] = pa1;
        *(uint4*)&sAl[ar*SKP + ak]     = pa2;
        *(uint4*)&sAl[ar*SKP + ak + 8] = pa3;
        if (doB) {
            *(uint4*)&sBh[br*SKP + bk]     = pb0;
            *(uint4*)&sBh[br*SKP + bk + 8] = pb1;
            *(uint4*)&sBl[br*SKP + bk]     = pb2;
            *(uint4*)&sBl[br*SKP + bk + 8] = pb3;
        }
        __syncthreads();
        if (kk + 32 < 256) fetch(kk + 32);
        #pragma unroll
        for (int kq = 0; kq < 32; kq += 16) {
            unsigned ah[2][4], al[2][4], bh[4][2], bl[4][2];
            #pragma unroll
            for (int i = 0; i < 2; ++i) {
                int row = wm*32 + i*16 + (lane & 15);
                int col = kq + ((lane >> 4) << 3);
                ldsm4(ah[i], &sAh[row*SKP + col]);
                ldsm4(al[i], &sAl[row*SKP + col]);
            }
            {
                int g = lane >> 3, r = lane & 7;
                int nrow = wn*32 + ((g >> 1) << 3) + r;
                int kcol = kq + ((g & 1) << 3);
                unsigned t0[4], t1[4], u0[4], u1[4];
                ldsm4(t0, &sBh[(nrow)      * SKP + kcol]);
                ldsm4(t1, &sBh[(nrow + 16) * SKP + kcol]);
                ldsm4(u0, &sBl[(nrow)      * SKP + kcol]);
                ldsm4(u1, &sBl[(nrow + 16) * SKP + kcol]);
                bh[0][0]=t0[0]; bh[0][1]=t0[1]; bh[1][0]=t0[2]; bh[1][1]=t0[3];
                bh[2][0]=t1[0]; bh[2][1]=t1[1]; bh[3][0]=t1[2]; bh[3][1]=t1[3];
                bl[0][0]=u0[0]; bl[0][1]=u0[1]; bl[1][0]=u0[2]; bl[1][1]=u0[3];
                bl[2][0]=u1[0]; bl[2][1]=u1[1]; bl[3][0]=u1[2]; bl[3][1]=u1[3];
            }
            #pragma unroll
            for (int i = 0; i < 2; ++i)
                #pragma unroll
                for (int j = 0; j < 4; ++j) {
                    mma16816(acc[i][j], ah[i], bh[j]);
                    mma16816(acc[i][j], al[i], bh[j]);
                    mma16816(acc[i][j], ah[i], bl[j]);
                }
        }
        __syncthreads();
    }
    #pragma unroll
    for (int i = 0; i < 2; ++i) {
        int r = wm*32 + i*16 + (lane >> 2);
        #pragma unroll
        for (int j = 0; j < 4; ++j) {
            int cc = wn*32 + j*8 + (lane & 3)*2;
            Cs[r*68 + cc]         = acc[i][j][0];
            Cs[r*68 + cc + 1]     = acc[i][j][1];
            Cs[(r+8)*68 + cc]     = acc[i][j][2];
            Cs[(r+8)*68 + cc + 1] = acc[i][j][3];
        }
    }
    __syncthreads();
    for (int idx = tid; idx < 96*64; idx += 192) {
        int r = idx >> 6, cc = idx & 63;
        float v = Cs[r*68 + cc] + bias[n0 + cc];
        if (ACT) v = tanh_fast(v);
        Out[(size_t)(m0 + r)*256 + n0 + cc] = v;
    }
}

// ------------------ persistent pure-fp16 scan -----------------------------------
// 128 CTAs: grp = cta>>3 rows m0=grp*96 (4 batches); nc = cta&7 gates n0=nc*128
// (units u0=nc*32). 12 warps, warp grid 3 rows(32) x 4 gates(32).
// Wh cached in smem whole kernel; acts staged via cp.async double-buffer.
__global__ __launch_bounds__(PTHREADS, 1)
void lstm_persist(const __half* __restrict__ Xh, const __half* __restrict__ Wh,
                  const float* __restrict__ bias, const float* __restrict__ Gmat,
                  const float* __restrict__ Cinit,
                  __half* __restrict__ GhH, __half* __restrict__ GhL)
{
    extern __shared__ __align__(16) char sm[];
    __half* sWh  = (__half*)(sm + SM_WH);
    float* sG    = (float*)(sm + SM_G);
    float* sBias = (float*)(sm + SM_BIAS);
    float* Hs    = (float*)(sm + SM_HS);
    float* Cs    = (float*)(sm + SM_UNION);
    const uint32_t smu = (uint32_t)__cvta_generic_to_shared(sm);

    const int tid = threadIdx.x, lane = tid & 31, warp = tid >> 5;
    const int wr = warp >> 2, wg = warp & 3;
    const int grp = blockIdx.x >> 3, nc = blockIdx.x & 7;
    const int m0 = grp*96, n0 = nc*128, u0 = nc*32;

    // one-time: Wh cache (128 gates x 512 k), G, bias, c
    for (int e = tid; e < 128*64; e += PTHREADS) {
        int r = e >> 6, kq = (e & 63) * 8;
        *(uint4*)&sWh[r*WSTR + kq] = *(const uint4*)(Wh + (size_t)(n0 + r)*KCAT + kq);
    }
    for (int i = tid; i < NN*NN; i += PTHREADS) sG[i] = Gmat[i];
    if (tid < 128) sBias[tid] = bias[n0 + tid];
    float creg[8];
    #pragma unroll
    for (int k = 0; k < 8; ++k) {
        int idx = tid + k*PTHREADS, r = idx >> 5, u = idx & 31;
        creg[k] = Cinit[(m0 + r)*HH + u0 + u];
    }
    __syncthreads();

    const int ar = tid >> 2, ak = (tid & 3) * 16;   // 96 rows x 64 k staging

    auto issue = [&](const __half* src, int kk, int buf) {
        uint32_t sb = smu + SM_UNION + buf*BUFB + (ar*ASTR + ak)*2;
        const __half* gp = src + (size_t)(m0 + ar)*256 + kk + ak;
        cp16(sb, gp);
        cp16(sb + 16, gp + 8);
        asm volatile("cp.async.commit_group;");
    };

    for (int t = 0; t < TT; ++t) {
        const int pi = t & 1, po = pi ^ 1;
        const __half* XhT = Xh + (size_t)t*ROWS*FF;
        const __half* GhHp = GhH + (size_t)pi*ROWS*HH;

        float acc[2][4][4];
        #pragma unroll
        for (int i = 0; i < 2; ++i)
            #pragma unroll
            for (int j = 0; j < 4; ++j)
                #pragma unroll
                for (int e = 0; e < 4; ++e) acc[i][j][e] = 0.f;

        auto compute = [&](int kw, int buf) {   // kw = global k base into sWh
            const __half* sB = (const __half*)(sm + SM_UNION + buf*BUFB);
            #pragma unroll
            for (int kq = 0; kq < 64; kq += 16) {
                unsigned a[2][4], w[4][2];
                #pragma unroll
                for (int i = 0; i < 2; ++i) {
                    int row = wr*32 + i*16 + (lane & 15);
                    int col = kq + ((lane >> 4) << 3);
                    ldsm4(a[i], &sB[row*ASTR + col]);
                }
                #pragma unroll
                for (int j2 = 0; j2 < 2; ++j2) {
                    int g = lane >> 3, r = lane & 7;
                    int grow = wg*32 + j2*16 + ((g >> 1) << 3) + r;
                    int kcol = kw + kq + ((g & 1) << 3);
                    unsigned tw[4];
                    ldsm4(tw, &sWh[grow*WSTR + kcol]);
                    w[j2*2][0]   = tw[0]; w[j2*2][1]   = tw[1];
                    w[j2*2+1][0] = tw[2]; w[j2*2+1][1] = tw[3];
                }
                #pragma unroll
                for (int i = 0; i < 2; ++i)
                    #pragma unroll
                    for (int j = 0; j < 4; ++j)
                        mma16816(acc[i][j], a[i], w[j]);
            }
        };

        // phase 1: k [0,256) from x(t)
        issue(XhT, 0, 0);
        #pragma unroll
        for (int c = 0; c < 4; ++c) {
            asm volatile("cp.async.wait_group 0;" ::: "memory");
            __syncthreads();
            if (c < 3) issue(XhT, (c + 1)*64, (c + 1) & 1);
            compute(c*64, c & 1);
        }
        // wait for all 8 peers to have published Gh(t)
        if (t > 0) {
            if (tid == 0) {
                unsigned v, tgt = 8u * (unsigned)t;
                while (1) {
                    asm volatile("ld.acquire.gpu.global.u32 %0, [%1];"
                                 : "=r"(v) : "l"(&g_bar[grp]) : "memory");
                    if (v >= tgt) break;
                    __nanosleep(32);
                }
            }
            __syncthreads();
        }
        // phase 2: k [256,512) from Gh(t)
        issue(GhHp, 0, 0);
        #pragma unroll
        for (int c = 0; c < 4; ++c) {
            asm volatile("cp.async.wait_group 0;" ::: "memory");
            __syncthreads();
            if (c < 3) issue(GhHp, (c + 1)*64, (c + 1) & 1);
            compute(256 + c*64, c & 1);
        }
        __syncthreads();   // all compute done before Cs overwrites staging

        // epilogue: acc -> Cs [row][gate]
        #pragma unroll
        for (int i = 0; i < 2; ++i) {
            int r = wr*32 + i*16 + (lane >> 2);
            #pragma unroll
            for (int j = 0; j < 4; ++j) {
                int cc = wg*32 + j*8 + (lane & 3)*2;
                Cs[r*132 + cc]         = acc[i][j][0];
                Cs[r*132 + cc + 1]     = acc[i][j][1];
                Cs[(r+8)*132 + cc]     = acc[i][j][2];
                Cs[(r+8)*132 + cc + 1] = acc[i][j][3];
            }
        }
        __syncthreads();
        // LSTM cell (c in registers)
        #pragma unroll
        for (int k = 0; k < 8; ++k) {
            int idx = tid + k*PTHREADS, r = idx >> 5, u = idx & 31;
            float4 gv = *(const float4*)&Cs[r*132 + 4*u];
            float4 bv = *(const float4*)&sBias[4*u];
            float vi = sigf(gv.x + bv.x);
            float vf = sigf(gv.y + bv.y);
            float vg = tanh_fast(gv.z + bv.z);
            float vo = sigf(gv.w + bv.w);
            float cv = vf * creg[k] + vi * vg;
            creg[k] = cv;
            Hs[r*33 + u] = vo * tanh_fast(cv);
        }
        __syncthreads();
        // node-mix fresh h -> Gh(po)
        #pragma unroll
        for (int k = 0; k < 8; ++k) {
            int idx = tid + k*PTHREADS, r = idx >> 5, u = idx & 31;
            int lb = r / NN, n = r - lb*NN;
            float a = 0.f;
            #pragma unroll
            for (int m = 0; m < NN; ++m) a += sG[n*NN + m] * Hs[(lb*NN + m)*33 + u];
            __half hv = __float2half_rn(a);
            size_t off = (size_t)(m0 + r)*HH + u0 + u;
            GhH[(size_t)po*ROWS*HH + off] = hv;
            if (t == TT - 1)   // lo residual for the final fc GEMM only
                GhL[off] = __float2half_rn(a - __half2float(hv));
        }
        __syncthreads();
        if (tid == 0)
            asm volatile("red.release.gpu.global.add.u32 [%0], %1;"
                         :: "l"(&g_bar[grp]), "r"(1u) : "memory");
    }
}

// ---------------------------------------------------------------------------
extern "C" void kernel_launch(void* const* d_in, const int* in_sizes, int n_in,
                              void* d_out, int out_size)
{
    const float* x    = (const float*)d_in[0];
    const float* G    = (const float*)d_in[1];
    const float* W_ih = (const float*)d_in[2];
    const float* b_ih = (const float*)d_in[3];
    const float* W_hh = (const float*)d_in[4];
    const float* b_hh = (const float*)d_in[5];
    const float* W_h1 = (const float*)d_in[6];
    const float* b_h1 = (const float*)d_in[7];
    const float* W_h2 = (const float*)d_in[8];
    const float* b_h2 = (const float*)d_in[9];
    const float* W_fc = (const float*)d_in[10];
    const float* b_fc = (const float*)d_in[11];
    float* out = (float*)d_out;

    __half *Xh, *Xl, *Ghh, *Ghl, *Wch, *W1h, *W1l, *W2h, *W2l, *Wfh, *Wfl;
    float *bcat, *h, *c;
    cudaGetSymbolAddress((void**)&Xh,  g_Xh);
    cudaGetSymbolAddress((void**)&Xl,  g_Xl);
    cudaGetSymbolAddress((void**)&Ghh, g_Ghh);
    cudaGetSymbolAddress((void**)&Ghl, g_Ghl);
    cudaGetSymbolAddress((void**)&Wch, g_Wch);
    cudaGetSymbolAddress((void**)&W1h, g_W1h);
    cudaGetSymbolAddress((void**)&W1l, g_W1l);
    cudaGetSymbolAddress((void**)&W2h, g_W2h);
    cudaGetSymbolAddress((void**)&W2l, g_W2l);
    cudaGetSymbolAddress((void**)&Wfh, g_Wfh);
    cudaGetSymbolAddress((void**)&Wfl, g_Wfl);
    cudaGetSymbolAddress((void**)&bcat, g_bcat);
    cudaGetSymbolAddress((void**)&h,   g_h);
    cudaGetSymbolAddress((void**)&c,   g_c);

    cudaFuncSetAttribute(lstm_persist, cudaFuncAttributeMaxDynamicSharedMemorySize, SM_TOTAL);

    // prep
    mix_x<<<BB*TT, 256>>>(x, G);
    pack_cat<<<(G4H*KCAT)/256, 256>>>(W_ih, W_hh, b_ih, b_hh);
    pack_w<<<(HH*FF)/256, 256>>>(W_h1, W1h, W1l);
    pack_w<<<(HH*FF)/256, 256>>>(W_h2, W2h, W2l);
    pack_w<<<(HH*HH)/256, 256>>>(W_fc, Wfh, Wfl);
    reset_bar<<<1, 32>>>();

    // h0 / c0 from t=0 slice of node-mixed x (3-term fp16 for precision)
    dim3 gSm(4, 16);
    mma_small<0><<<gSm, 192>>>(Xh, Xl, W1h, W1l, b_h1, h);
    mma_small<0><<<gSm, 192>>>(Xh, Xl, W2h, W2l, b_h2, c);
    mix_h<<<BB, 256>>>(G, Ghh);   // Gh(0) hi -> buffer 0

    // persistent pure-fp16 scan (50 steps)
    lstm_persist<<<128, PTHREADS, SM_TOTAL>>>(Xh, Wch, bcat, G, c, Ghh, Ghl);

    // output: tanh((G h) @ W_fc^T + b_fc); after 50 steps Gh is in buffer 0
    mma_small<1><<<gSm, 192>>>(Ghh, Ghl, Wfh, Wfl, b_fc, out);
}

// round 9
// speedup vs baseline: 5.8434x; 1.0513x over previous
#include <cuda_runtime.h>
#include <cuda_fp16.h>
#include <math.h>
#include <stdint.h>

#define BB 64
#define TT 50
#define NN 24
#define FF 256
#define HH 256
#define G4H 1024
#define ROWS 1536
#define KCAT 512
#define SKP 40       // mma_small staging stride
#define WSTR 520     // persistent Wh cache row stride (fp16) — conflict-free
#define ASTR 72      // act staging row stride (fp16) — conflict-free
#define PTHREADS 384

// ---- persistent smem layout (bytes) ----
#define SM_WH    0                       // 128*WSTR*2 = 133120
#define SM_G     133120                  // 2304
#define SM_BIAS  135424                  // 512
#define SM_HS    135936                  // 96*33*4 = 12672
#define SM_STAGE 148608                  // 2 x 13824 act staging
#define BUFB     13824
#define SM_TOTAL (SM_STAGE + 2*BUFB)     // 176256 B

// ------------------ device scratch ------------------------------------------
__device__ __half g_Xh[(size_t)TT*ROWS*FF];
__device__ __half g_Xl[ROWS*FF];             // t=0 slice only (h0/c0 precision)
__device__ __half g_Ghh[2][ROWS*HH];
__device__ __half g_Ghl[ROWS*HH];            // written at t=TT-1 only
__device__ __half g_Wch[(size_t)G4H*KCAT];   // [W_ih|W_hh] gate-interleaved fp16
__device__ __half g_W1h[HH*FF], g_W1l[HH*FF];
__device__ __half g_W2h[HH*FF], g_W2l[HH*FF];
__device__ __half g_Wfh[HH*HH], g_Wfl[HH*HH];
__device__ float g_bcat[G4H];
__device__ float g_h[ROWS*HH];
__device__ float g_c[ROWS*HH];
__device__ unsigned g_bar[16];

// ------------------ helpers --------------------------------------------------
__device__ __forceinline__ float sigf(float x) { return 1.f / (1.f + __expf(-x)); }
__device__ __forceinline__ float tanh_fast(float x) {
    float ax = fabsf(x);
    float t = __expf(-2.f * ax);
    return copysignf((1.f - t) / (1.f + t), x);
}
__device__ __forceinline__ void mma16816(float* d, const unsigned* a, const unsigned* b) {
    asm volatile("mma.sync.aligned.m16n8k16.row.col.f32.f16.f16.f32 "
                 "{%0,%1,%2,%3},{%4,%5,%6,%7},{%8,%9},{%0,%1,%2,%3};"
                 : "+f"(d[0]), "+f"(d[1]), "+f"(d[2]), "+f"(d[3])
                 : "r"(a[0]), "r"(a[1]), "r"(a[2]), "r"(a[3]), "r"(b[0]), "r"(b[1]));
}
__device__ __forceinline__ void ldsm4(unsigned* r, const __half* p) {
    unsigned addr = (unsigned)__cvta_generic_to_shared(p);
    asm volatile("ldmatrix.sync.aligned.m8n8.x4.shared.b16 {%0,%1,%2,%3},[%4];"
                 : "=r"(r[0]), "=r"(r[1]), "=r"(r[2]), "=r"(r[3]) : "r"(addr));
}
__device__ __forceinline__ void cp16(uint32_t s, const void* g) {
    asm volatile("cp.async.cg.shared.global [%0], [%1], 16;" :: "r"(s), "l"(g));
}

// ------------------ packing ---------------------------------------------------
// packed col n = 4*j + q ; original weight row r = q*256 + j  (q: i,f,g,o)
__global__ __launch_bounds__(256)
void pack_cat(const float* __restrict__ Wih, const float* __restrict__ Whh,
              const float* __restrict__ bih, const float* __restrict__ bhh)
{
    if (blockIdx.x == 0 && threadIdx.x < 16) g_bar[threadIdx.x] = 0u;
    int idx = blockIdx.x * 256 + threadIdx.x;
    int n = idx >> 9, k = idx & 511;
    int r = (n & 3) * HH + (n >> 2);
    float v = (k < 256) ? Wih[r*256 + k] : Whh[r*256 + (k - 256)];
    g_Wch[idx] = __float2half_rn(v);
    if (k == 0) g_bcat[n] = bih[r] + bhh[r];
}
// fused hi/lo pack of W_h1, W_h2, W_fc (all 256x256)
__global__ __launch_bounds__(256)
void pack_all(const float* __restrict__ W1, const float* __restrict__ W2,
              const float* __restrict__ Wf)
{
    int b = blockIdx.x;
    int idx = (b & 255) * 256 + threadIdx.x;
    const float* W; __half *Wh, *Wl;
    if (b < 256)      { W = W1; Wh = g_W1h; Wl = g_W1l; }
    else if (b < 512) { W = W2; Wh = g_W2h; Wl = g_W2l; }
    else              { W = Wf; Wh = g_Wfh; Wl = g_Wfl; }
    float v = W[idx];
    __half hv = __float2half_rn(v);
    Wh[idx] = hv;
    Wl[idx] = __float2half_rn(v - __half2float(hv));
}

// ------------------ node-mix ---------------------------------------------------
__global__ __launch_bounds__(256)
void mix_x(const float* __restrict__ x, const float* __restrict__ G)
{
    __shared__ float xs[NN*FF];
    __shared__ float Gs[NN*NN];
    int bid = blockIdx.x, t = bid / BB, b = bid % BB;
    const float* xin = x + (size_t)(b*TT + t) * NN * FF;
    size_t ob = (size_t)bid * NN * FF;
    int tid = threadIdx.x;
    for (int i = tid; i < NN*FF; i += 256) xs[i] = xin[i];
    for (int i = tid; i < NN*NN; i += 256) Gs[i] = G[i];
    __syncthreads();
    for (int i = tid; i < NN*FF; i += 256) {
        int n = i >> 8, f = i & 255;
        float a = 0.f;
        #pragma unroll
        for (int m = 0; m < NN; ++m) a += Gs[n*NN + m] * xs[m*FF + f];
        __half hv = __float2half_rn(a);
        g_Xh[ob + i] = hv;
        if (bid < BB)   // t==0 slice keeps lo residual for h0/c0 precision
            g_Xl[ob + i] = __float2half_rn(a - __half2float(hv));
    }
}
__global__ __launch_bounds__(256)
void mix_h(const float* __restrict__ G, __half* __restrict__ oh)
{
    __shared__ float hs[NN*HH];
    __shared__ float Gs[NN*NN];
    int b = blockIdx.x, tid = threadIdx.x;
    const float* hin = g_h + (size_t)b * NN * HH;
    size_t ob = (size_t)b * NN * HH;
    for (int i = tid; i < NN*HH; i += 256) hs[i] = hin[i];
    for (int i = tid; i < NN*NN; i += 256) Gs[i] = G[i];
    __syncthreads();
    for (int i = tid; i < NN*HH; i += 256) {
        int n = i >> 8, f = i & 255;
        float a = 0.f;
        #pragma unroll
        for (int m = 0; m < NN; ++m) a += Gs[n*NN + m] * hs[m*HH + f];
        oh[ob + i] = __float2half_rn(a);
    }
}

// ------------------ small GEMM (h0/c0/final), fp16 3-term ----------------------
template<int ACT>
__global__ __launch_bounds__(192)
void mma_small(const __half* __restrict__ Ah, const __half* __restrict__ Al,
               const __half* __restrict__ Bh0, const __half* __restrict__ Bl0,
               const float* __restrict__ bias, float* __restrict__ Out)
{
    __shared__ __align__(16) char smbuf[26624];
    __half* sAh = (__half*)smbuf;
    __half* sAl = sAh + 96*SKP;
    __half* sBh = sAl + 96*SKP;
    __half* sBl = sBh + 64*SKP;
    float* Cs = (float*)smbuf;

    int tid = threadIdx.x, lane = tid & 31, warp = tid >> 5;
    int wm = warp >> 1, wn = warp & 1;
    int m0 = blockIdx.y * 96, n0 = blockIdx.x * 64;

    float acc[2][4][4] = {};
    int ar = tid >> 1, ak = (tid & 1) * 16;
    int br = tid >> 1, bk = (tid & 1) * 16;
    bool doB = tid < 128;
    uint4 pa0, pa1, pa2, pa3, pb0, pb1, pb2, pb3;

    auto fetch = [&](int kk) {
        const __half* gH = Ah + (size_t)(m0 + ar)*256 + kk + ak;
        const __half* gL = Al + (size_t)(m0 + ar)*256 + kk + ak;
        pa0 = *(const uint4*)gH; pa1 = *(const uint4*)(gH + 8);
        pa2 = *(const uint4*)gL; pa3 = *(const uint4*)(gL + 8);
        if (doB) {
            const __half* gBh = Bh0 + (size_t)(n0 + br)*256 + kk + bk;
            const __half* gBl = Bl0 + (size_t)(n0 + br)*256 + kk + bk;
            pb0 = *(const uint4*)gBh; pb1 = *(const uint4*)(gBh + 8);
            pb2 = *(const uint4*)gBl; pb3 = *(const uint4*)(gBl + 8);
        }
    };
    fetch(0);
    for (int kk = 0; kk < 256; kk += 32) {
        *(uint4*)&sAh[ar*SKP + ak]     = pa0;
        *(uint4*)&sAh[ar*SKP + ak + 8] = pa1;
        *(uint4*)&sAl[ar*SKP + ak]     = pa2;
        *(uint4*)&sAl[ar*SKP + ak + 8] = pa3;
        if (doB) {
            *(uint4*)&sBh[br*SKP + bk]     = pb0;
            *(uint4*)&sBh[br*SKP + bk + 8] = pb1;
            *(uint4*)&sBl[br*SKP + bk]     = pb2;
            *(uint4*)&sBl[br*SKP + bk + 8] = pb3;
        }
        __syncthreads();
        if (kk + 32 < 256) fetch(kk + 32);
        #pragma unroll
        for (int kq = 0; kq < 32; kq += 16) {
            unsigned ah[2][4], al[2][4], bh[4][2], bl[4][2];
            #pragma unroll
            for (int i = 0; i < 2; ++i) {
                int row = wm*32 + i*16 + (lane & 15);
                int col = kq + ((lane >> 4) << 3);
                ldsm4(ah[i], &sAh[row*SKP + col]);
                ldsm4(al[i], &sAl[row*SKP + col]);
            }
            {
                int g = lane >> 3, r = lane & 7;
                int nrow = wn*32 + ((g >> 1) << 3) + r;
                int kcol = kq + ((g & 1) << 3);
                unsigned t0[4], t1[4], u0[4], u1[4];
                ldsm4(t0, &sBh[(nrow)      * SKP + kcol]);
                ldsm4(t1, &sBh[(nrow + 16) * SKP + kcol]);
                ldsm4(u0, &sBl[(nrow)      * SKP + kcol]);
                ldsm4(u1, &sBl[(nrow + 16) * SKP + kcol]);
                bh[0][0]=t0[0]; bh[0][1]=t0[1]; bh[1][0]=t0[2]; bh[1][1]=t0[3];
                bh[2][0]=t1[0]; bh[2][1]=t1[1]; bh[3][0]=t1[2]; bh[3][1]=t1[3];
                bl[0][0]=u0[0]; bl[0][1]=u0[1]; bl[1][0]=u0[2]; bl[1][1]=u0[3];
                bl[2][0]=u1[0]; bl[2][1]=u1[1]; bl[3][0]=u1[2]; bl[3][1]=u1[3];
            }
            #pragma unroll
            for (int i = 0; i < 2; ++i)
                #pragma unroll
                for (int j = 0; j < 4; ++j) {
                    mma16816(acc[i][j], ah[i], bh[j]);
                    mma16816(acc[i][j], al[i], bh[j]);
                    mma16816(acc[i][j], ah[i], bl[j]);
                }
        }
        __syncthreads();
    }
    #pragma unroll
    for (int i = 0; i < 2; ++i) {
        int r = wm*32 + i*16 + (lane >> 2);
        #pragma unroll
        for (int j = 0; j < 4; ++j) {
            int cc = wn*32 + j*8 + (lane & 3)*2;
            Cs[r*68 + cc]         = acc[i][j][0];
            Cs[r*68 + cc + 1]     = acc[i][j][1];
            Cs[(r+8)*68 + cc]     = acc[i][j][2];
            Cs[(r+8)*68 + cc + 1] = acc[i][j][3];
        }
    }
    __syncthreads();
    for (int idx = tid; idx < 96*64; idx += 192) {
        int r = idx >> 6, cc = idx & 63;
        float v = Cs[r*68 + cc] + bias[n0 + cc];
        if (ACT) v = tanh_fast(v);
        Out[(size_t)(m0 + r)*256 + n0 + cc] = v;
    }
}

// ------------------ persistent pure-fp16 scan -----------------------------------
// 128 CTAs: grp = cta>>3 rows m0=grp*96 (4 batches); nc = cta&7 gates n0=nc*128
// (units u0=nc*32). 12 warps, warp grid 3 rows(32) x 4 gates(32).
// Wh cached in smem; acts via cp.async double-buffer; cell fused via shfl-quad.
__global__ __launch_bounds__(PTHREADS, 1)
void lstm_persist(const __half* __restrict__ Xh, const __half* __restrict__ Wh,
                  const float* __restrict__ bias, const float* __restrict__ Gmat,
                  const float* __restrict__ Cinit,
                  __half* __restrict__ GhH, __half* __restrict__ GhL)
{
    extern __shared__ __align__(16) char sm[];
    __half* sWh  = (__half*)(sm + SM_WH);
    float* sG    = (float*)(sm + SM_G);
    float* sBias = (float*)(sm + SM_BIAS);
    float* Hs    = (float*)(sm + SM_HS);
    const uint32_t smu = (uint32_t)__cvta_generic_to_shared(sm);

    const int tid = threadIdx.x, lane = tid & 31, warp = tid >> 5;
    const int wr = warp >> 2, wg = warp & 3;
    const int grp = blockIdx.x >> 3, nc = blockIdx.x & 7;
    const int m0 = grp*96, n0 = nc*128, u0 = nc*32;
    const int p = lane & 1;

    // one-time: Wh cache, G, bias, c (c in MMA-fragment layout)
    for (int e = tid; e < 128*64; e += PTHREADS) {
        int r = e >> 6, kq = (e & 63) * 8;
        *(uint4*)&sWh[r*WSTR + kq] = *(const uint4*)(Wh + (size_t)(n0 + r)*KCAT + kq);
    }
    for (int i = tid; i < NN*NN; i += PTHREADS) sG[i] = Gmat[i];
    if (tid < 128) sBias[tid] = bias[n0 + tid];
    float creg[8];
    #pragma unroll
    for (int i = 0; i < 2; ++i)
        #pragma unroll
        for (int j = 0; j < 4; ++j) {
            int row = wr*32 + i*16 + (lane >> 2) + 8*p;
            int uu  = wg*8 + 2*j + ((lane & 3) >> 1);
            creg[i*4 + j] = Cinit[(m0 + row)*HH + u0 + uu];
        }
    __syncthreads();

    const int ar = tid >> 2, ak = (tid & 3) * 16;   // 96 rows x 64 k staging

    auto issue = [&](const __half* src, int kk, int buf) {
        uint32_t sb = smu + SM_STAGE + buf*BUFB + (ar*ASTR + ak)*2;
        const __half* gp = src + (size_t)(m0 + ar)*256 + kk + ak;
        cp16(sb, gp);
        cp16(sb + 16, gp + 8);
        asm volatile("cp.async.commit_group;");
    };

    issue(Xh, 0, 0);   // prefetch t=0 phase-1 chunk0

    for (int t = 0; t < TT; ++t) {
        const int pi = t & 1, po = pi ^ 1;
        const __half* XhT = Xh + (size_t)t*ROWS*FF;
        const __half* GhHp = GhH + (size_t)pi*ROWS*HH;

        float acc[2][4][4];
        #pragma unroll
        for (int i = 0; i < 2; ++i)
            #pragma unroll
            for (int j = 0; j < 4; ++j)
                #pragma unroll
                for (int e = 0; e < 4; ++e) acc[i][j][e] = 0.f;

        auto compute = [&](int kw, int buf) {   // kw = global k base into sWh
            const __half* sB = (const __half*)(sm + SM_STAGE + buf*BUFB);
            #pragma unroll
            for (int kq = 0; kq < 64; kq += 16) {
                unsigned a[2][4], w[4][2];
                #pragma unroll
                for (int i = 0; i < 2; ++i) {
                    int row = wr*32 + i*16 + (lane & 15);
                    int col = kq + ((lane >> 4) << 3);
                    ldsm4(a[i], &sB[row*ASTR + col]);
                }
                #pragma unroll
                for (int j2 = 0; j2 < 2; ++j2) {
                    int g = lane >> 3, r = lane & 7;
                    int grow = wg*32 + j2*16 + ((g >> 1) << 3) + r;
                    int kcol = kw + kq + ((g & 1) << 3);
                    unsigned tw[4];
                    ldsm4(tw, &sWh[grow*WSTR + kcol]);
                    w[j2*2][0]   = tw[0]; w[j2*2][1]   = tw[1];
                    w[j2*2+1][0] = tw[2]; w[j2*2+1][1] = tw[3];
                }
                #pragma unroll
                for (int i = 0; i < 2; ++i)
                    #pragma unroll
                    for (int j = 0; j < 4; ++j)
                        mma16816(acc[i][j], a[i], w[j]);
            }
        };

        // phase 1: k [0,256) from x(t) (chunk0 already prefetched)
        #pragma unroll
        for (int c = 0; c < 4; ++c) {
            asm volatile("cp.async.wait_group 0;" ::: "memory");
            __syncthreads();
            if (c < 3) issue(XhT, (c + 1)*64, (c + 1) & 1);
            compute(c*64, c & 1);
        }
        // wait for all 8 peers to have published Gh(t)
        if (t > 0) {
            if (tid == 0) {
                unsigned v, tgt = 8u * (unsigned)t;
                while (1) {
                    asm volatile("ld.acquire.gpu.global.u32 %0, [%1];"
                                 : "=r"(v) : "l"(&g_bar[grp]) : "memory");
                    if (v >= tgt) break;
                    __nanosleep(32);
                }
            }
            __syncthreads();
        }
        // phase 2: k [256,512) from Gh(t)
        issue(GhHp, 0, 0);
        #pragma unroll
        for (int c = 0; c < 4; ++c) {
            asm volatile("cp.async.wait_group 0;" ::: "memory");
            __syncthreads();
            if (c < 3) issue(GhHp, (c + 1)*64, (c + 1) & 1);
            compute(256 + c*64, c & 1);
        }

        // prefetch next step's phase-1 chunk0 during epilogue
        // (buf0 free: last read at phase-2 c=2, fenced by the c=3 syncthreads)
        if (t + 1 < TT) issue(XhT + ROWS*FF, 0, 0);

        // ---- fused epilogue: shfl-quad assembly + LSTM cell (c in regs) ----
        #pragma unroll
        for (int i = 0; i < 2; ++i)
            #pragma unroll
            for (int j = 0; j < 4; ++j) {
                float d0 = acc[i][j][0], d1 = acc[i][j][1];
                float d2 = acc[i][j][2], d3 = acc[i][j][3];
                float s0 = __shfl_xor_sync(0xffffffffu, p ? d0 : d2, 1);
                float s1 = __shfl_xor_sync(0xffffffffu, p ? d1 : d3, 1);
                float qi = p ? s0 : d0, qf = p ? s1 : d1;
                float qg = p ? d2 : s0, qo = p ? d3 : s1;
                int row = wr*32 + i*16 + (lane >> 2) + 8*p;
                int uu  = wg*8 + 2*j + ((lane & 3) >> 1);
                float4 bv = *(const float4*)&sBias[4*uu];
                float vi = sigf(qi + bv.x);
                float vf = sigf(qf + bv.y);
                float vg = tanh_fast(qg + bv.z);
                float vo = sigf(qo + bv.w);
                float cv = vf * creg[i*4 + j] + vi * vg;
                creg[i*4 + j] = cv;
                Hs[row*33 + uu] = vo * tanh_fast(cv);
            }
        __syncthreads();
        // node-mix fresh h -> Gh(po)
        #pragma unroll
        for (int k = 0; k < 8; ++k) {
            int idx = tid + k*PTHREADS, r = idx >> 5, u = idx & 31;
            int lb = r / NN, n = r - lb*NN;
            float a = 0.f;
            #pragma unroll
            for (int m = 0; m < NN; ++m) a += sG[n*NN + m] * Hs[(lb*NN + m)*33 + u];
            __half hv = __float2half_rn(a);
            size_t off = (size_t)(m0 + r)*HH + u0 + u;
            GhH[(size_t)po*ROWS*HH + off] = hv;
            if (t == TT - 1)   // lo residual for the final fc GEMM only
                GhL[off] = __float2half_rn(a - __half2float(hv));
        }
        __syncthreads();
        if (tid == 0)
            asm volatile("red.release.gpu.global.add.u32 [%0], %1;"
                         :: "l"(&g_bar[grp]), "r"(1u) : "memory");
    }
}

// ---------------------------------------------------------------------------
extern "C" void kernel_launch(void* const* d_in, const int* in_sizes, int n_in,
                              void* d_out, int out_size)
{
    const float* x    = (const float*)d_in[0];
    const float* G    = (const float*)d_in[1];
    const float* W_ih = (const float*)d_in[2];
    const float* b_ih = (const float*)d_in[3];
    const float* W_hh = (const float*)d_in[4];
    const float* b_hh = (const float*)d_in[5];
    const float* W_h1 = (const float*)d_in[6];
    const float* b_h1 = (const float*)d_in[7];
    const float* W_h2 = (const float*)d_in[8];
    const float* b_h2 = (const float*)d_in[9];
    const float* W_fc = (const float*)d_in[10];
    const float* b_fc = (const float*)d_in[11];
    float* out = (float*)d_out;

    __half *Xh, *Xl, *Ghh, *Ghl, *Wch, *W1h, *W1l, *W2h, *W2l, *Wfh, *Wfl;
    float *bcat, *h, *c;
    cudaGetSymbolAddress((void**)&Xh,  g_Xh);
    cudaGetSymbolAddress((void**)&Xl,  g_Xl);
    cudaGetSymbolAddress((void**)&Ghh, g_Ghh);
    cudaGetSymbolAddress((void**)&Ghl, g_Ghl);
    cudaGetSymbolAddress((void**)&Wch, g_Wch);
    cudaGetSymbolAddress((void**)&W1h, g_W1h);
    cudaGetSymbolAddress((void**)&W1l, g_W1l);
    cudaGetSymbolAddress((void**)&W2h, g_W2h);
    cudaGetSymbolAddress((void**)&W2l, g_W2l);
    cudaGetSymbolAddress((void**)&Wfh, g_Wfh);
    cudaGetSymbolAddress((void**)&Wfl, g_Wfl);
    cudaGetSymbolAddress((void**)&bcat, g_bcat);
    cudaGetSymbolAddress((void**)&h,   g_h);
    cudaGetSymbolAddress((void**)&c,   g_c);

    cudaFuncSetAttribute(lstm_persist, cudaFuncAttributeMaxDynamicSharedMemorySize, SM_TOTAL);

    // prep
    mix_x<<<BB*TT, 256>>>(x, G);
    pack_cat<<<(G4H*KCAT)/256, 256>>>(W_ih, W_hh, b_ih, b_hh);
    pack_all<<<768, 256>>>(W_h1, W_h2, W_fc);

    // h0 / c0 from t=0 slice of node-mixed x (3-term fp16 for precision)
    dim3 gSm(4, 16);
    mma_small<0><<<gSm, 192>>>(Xh, Xl, W1h, W1l, b_h1, h);
    mma_small<0><<<gSm, 192>>>(Xh, Xl, W2h, W2l, b_h2, c);
    mix_h<<<BB, 256>>>(G, Ghh);   // Gh(0) hi -> buffer 0

    // persistent pure-fp16 scan (50 steps)
    lstm_persist<<<128, PTHREADS, SM_TOTAL>>>(Xh, Wch, bcat, G, c, Ghh, Ghl);

    // output: tanh((G h) @ W_fc^T + b_fc); after 50 steps Gh is in buffer 0
    mma_small<1><<<gSm, 192>>>(Ghh, Ghl, Wfh, Wfl, b_fc, out);
}

// round 11
// speedup vs baseline: 5.9796x; 1.0233x over previous
#include <cuda_runtime.h>
#include <cuda_fp16.h>
#include <math.h>
#include <stdint.h>

#define BB 64
#define TT 50
#define NN 24
#define FF 256
#define HH 256
#define G4H 1024
#define ROWS 1536
#define KCAT 512
#define SKP 40       // mma_small staging stride
#define WSTR 520     // persistent Wh cache row stride (fp16) — conflict-free
#define ASTR 72      // act staging row stride (fp16) — conflict-free
#define PTHREADS 384
#define HSTR 36      // Hs row stride (floats), 16B-aligned rows

// ---- persistent smem layout (bytes) ----
#define SM_WH    0                       // 128*WSTR*2 = 133120
#define SM_G     133120                  // 2304
#define SM_BIAS  135424                  // 512
#define SM_HS    135936                  // 96*HSTR*4 = 13824
#define SM_STAGE 149760                  // 2 x 13824 act staging
#define BUFB     13824
#define SM_TOTAL (SM_STAGE + 2*BUFB)     // 177408 B

// ------------------ device scratch ------------------------------------------
__device__ __half g_Xh[(size_t)TT*ROWS*FF];
__device__ __half g_Xl[ROWS*FF];             // t=0 slice only (h0/c0 precision)
__device__ __half g_Ghh[2][ROWS*HH];
__device__ __half g_Ghl[ROWS*HH];            // written at t=TT-1 only
__device__ __half g_Wch[(size_t)G4H*KCAT];   // [W_ih|W_hh] gate-interleaved fp16
__device__ __half g_W1h[HH*FF], g_W1l[HH*FF];
__device__ __half g_W2h[HH*FF], g_W2l[HH*FF];
__device__ __half g_Wfh[HH*HH], g_Wfl[HH*HH];
__device__ float g_bcat[G4H];
__device__ float g_h[ROWS*HH];
__device__ float g_c[ROWS*HH];
__device__ unsigned g_bar[16];

// ------------------ helpers --------------------------------------------------
__device__ __forceinline__ float sigf(float x) { return 1.f / (1.f + __expf(-x)); }
__device__ __forceinline__ float tanh_fast(float x) {
    float ax = fabsf(x);
    float t = __expf(-2.f * ax);
    return copysignf((1.f - t) / (1.f + t), x);
}
__device__ __forceinline__ void mma16816(float* d, const unsigned* a, const unsigned* b) {
    asm volatile("mma.sync.aligned.m16n8k16.row.col.f32.f16.f16.f32 "
                 "{%0,%1,%2,%3},{%4,%5,%6,%7},{%8,%9},{%0,%1,%2,%3};"
                 : "+f"(d[0]), "+f"(d[1]), "+f"(d[2]), "+f"(d[3])
                 : "r"(a[0]), "r"(a[1]), "r"(a[2]), "r"(a[3]), "r"(b[0]), "r"(b[1]));
}
__device__ __forceinline__ void ldsm4(unsigned* r, const __half* p) {
    unsigned addr = (unsigned)__cvta_generic_to_shared(p);
    asm volatile("ldmatrix.sync.aligned.m8n8.x4.shared.b16 {%0,%1,%2,%3},[%4];"
                 : "=r"(r[0]), "=r"(r[1]), "=r"(r[2]), "=r"(r[3]) : "r"(addr));
}
__device__ __forceinline__ void cp16(uint32_t s, const void* g) {
    asm volatile("cp.async.cg.shared.global [%0], [%1], 16;" :: "r"(s), "l"(g));
}
__device__ __forceinline__ unsigned pack2h(float a, float b) {
    __half2 h = __floats2half2_rn(a, b);
    return *(unsigned*)&h;
}

// ------------------ packing ---------------------------------------------------
// packed col n = 4*j + q ; original weight row r = q*256 + j  (q: i,f,g,o)
__global__ __launch_bounds__(256)
void pack_cat(const float* __restrict__ Wih, const float* __restrict__ Whh,
              const float* __restrict__ bih, const float* __restrict__ bhh)
{
    if (blockIdx.x == 0 && threadIdx.x < 16) g_bar[threadIdx.x] = 0u;
    int idx = blockIdx.x * 256 + threadIdx.x;
    int n = idx >> 9, k = idx & 511;
    int r = (n & 3) * HH + (n >> 2);
    float v = (k < 256) ? Wih[r*256 + k] : Whh[r*256 + (k - 256)];
    g_Wch[idx] = __float2half_rn(v);
    if (k == 0) g_bcat[n] = bih[r] + bhh[r];
}
// fused hi/lo pack of W_h1, W_h2, W_fc (all 256x256)
__global__ __launch_bounds__(256)
void pack_all(const float* __restrict__ W1, const float* __restrict__ W2,
              const float* __restrict__ Wf)
{
    int b = blockIdx.x;
    int idx = (b & 255) * 256 + threadIdx.x;
    const float* W; __half *Wh, *Wl;
    if (b < 256)      { W = W1; Wh = g_W1h; Wl = g_W1l; }
    else if (b < 512) { W = W2; Wh = g_W2h; Wl = g_W2l; }
    else              { W = Wf; Wh = g_Wfh; Wl = g_Wfl; }
    float v = W[idx];
    __half hv = __float2half_rn(v);
    Wh[idx] = hv;
    Wl[idx] = __float2half_rn(v - __half2float(hv));
}

// ------------------ node-mix ---------------------------------------------------
__global__ __launch_bounds__(256)
void mix_x(const float* __restrict__ x, const float* __restrict__ G)
{
    __shared__ float xs[NN*FF];
    __shared__ float Gs[NN*NN];
    int bid = blockIdx.x, t = bid / BB, b = bid % BB;
    const float* xin = x + (size_t)(b*TT + t) * NN * FF;
    size_t ob = (size_t)bid * NN * FF;
    int tid = threadIdx.x;
    for (int i = tid; i < NN*FF; i += 256) xs[i] = xin[i];
    for (int i = tid; i < NN*NN; i += 256) Gs[i] = G[i];
    __syncthreads();
    for (int i = tid; i < NN*FF; i += 256) {
        int n = i >> 8, f = i & 255;
        float a = 0.f;
        #pragma unroll
        for (int m = 0; m < NN; ++m) a += Gs[n*NN + m] * xs[m*FF + f];
        __half hv = __float2half_rn(a);
        g_Xh[ob + i] = hv;
        if (bid < BB)
            g_Xl[ob + i] = __float2half_rn(a - __half2float(hv));
    }
}
__global__ __launch_bounds__(256)
void mix_h(const float* __restrict__ G, __half* __restrict__ oh)
{
    __shared__ float hs[NN*HH];
    __shared__ float Gs[NN*NN];
    int b = blockIdx.x, tid = threadIdx.x;
    const float* hin = g_h + (size_t)b * NN * HH;
    size_t ob = (size_t)b * NN * HH;
    for (int i = tid; i < NN*HH; i += 256) hs[i] = hin[i];
    for (int i = tid; i < NN*NN; i += 256) Gs[i] = G[i];
    __syncthreads();
    for (int i = tid; i < NN*HH; i += 256) {
        int n = i >> 8, f = i & 255;
        float a = 0.f;
        #pragma unroll
        for (int m = 0; m < NN; ++m) a += Gs[n*NN + m] * hs[m*HH + f];
        oh[ob + i] = __float2half_rn(a);
    }
}

// ------------------ small GEMM (h0/c0 fused via z, final), fp16 3-term ---------
template<int ACT>
__global__ __launch_bounds__(192)
void mma_small(const __half* __restrict__ Ah, const __half* __restrict__ Al,
               const __half* __restrict__ Bh_0, const __half* __restrict__ Bl_0,
               const float* __restrict__ bias0, float* __restrict__ Out0,
               const __half* __restrict__ Bh_1, const __half* __restrict__ Bl_1,
               const float* __restrict__ bias1, float* __restrict__ Out1)
{
    __shared__ __align__(16) char smbuf[26624];
    __half* sAh = (__half*)smbuf;
    __half* sAl = sAh + 96*SKP;
    __half* sBh = sAl + 96*SKP;
    __half* sBl = sBh + 64*SKP;
    float* Cs = (float*)smbuf;

    const __half* Bh0 = blockIdx.z ? Bh_1 : Bh_0;
    const __half* Bl0 = blockIdx.z ? Bl_1 : Bl_0;
    const float* bias = blockIdx.z ? bias1 : bias0;
    float* Out        = blockIdx.z ? Out1  : Out0;

    int tid = threadIdx.x, lane = tid & 31, warp = tid >> 5;
    int wm = warp >> 1, wn = warp & 1;
    int m0 = blockIdx.y * 96, n0 = blockIdx.x * 64;

    float acc[2][4][4] = {};
    int ar = tid >> 1, ak = (tid & 1) * 16;
    int br = tid >> 1, bk = (tid & 1) * 16;
    bool doB = tid < 128;
    uint4 pa0, pa1, pa2, pa3, pb0, pb1, pb2, pb3;

    auto fetch = [&](int kk) {
        const __half* gH = Ah + (size_t)(m0 + ar)*256 + kk + ak;
        const __half* gL = Al + (size_t)(m0 + ar)*256 + kk + ak;
        pa0 = *(const uint4*)gH; pa1 = *(const uint4*)(gH + 8);
        pa2 = *(const uint4*)gL; pa3 = *(const uint4*)(gL + 8);
        if (doB) {
            const __half* gBh = Bh0 + (size_t)(n0 + br)*256 + kk + bk;
            const __half* gBl = Bl0 + (size_t)(n0 + br)*256 + kk + bk;
            pb0 = *(const uint4*)gBh; pb1 = *(const uint4*)(gBh + 8);
            pb2 = *(const uint4*)gBl; pb3 = *(const uint4*)(gBl + 8);
        }
    };
    fetch(0);
    for (int kk = 0; kk < 256; kk += 32) {
        *(uint4*)&sAh[ar*SKP + ak]     = pa0;
        *(uint4*)&sAh[ar*SKP + ak + 8] = pa1;
        *(uint4*)&sAl[ar*SKP + ak]     = pa2;
        *(uint4*)&sAl[ar*SKP + ak + 8] = pa3;
        if (doB) {
            *(uint4*)&sBh[br*SKP + bk]     = pb0;
            *(uint4*)&sBh[br*SKP + bk + 8] = pb1;
            *(uint4*)&sBl[br*SKP + bk]     = pb2;
            *(uint4*)&sBl[br*SKP + bk + 8] = pb3;
        }
        __syncthreads();
        if (kk + 32 < 256) fetch(kk + 32);
        #pragma unroll
        for (int kq = 0; kq < 32; kq += 16) {
            unsigned ah[2][4], al[2][4], bh[4][2], bl[4][2];
            #pragma unroll
            for (int i = 0; i < 2; ++i) {
                int row = wm*32 + i*16 + (lane & 15);
                int col = kq + ((lane >> 4) << 3);
                ldsm4(ah[i], &sAh[row*SKP + col]);
                ldsm4(al[i], &sAl[row*SKP + col]);
            }
            {
                int g = lane >> 3, r = lane & 7;
                int nrow = wn*32 + ((g >> 1) << 3) + r;
                int kcol = kq + ((g & 1) << 3);
                unsigned t0[4], t1[4], u0[4], u1[4];
                ldsm4(t0, &sBh[(nrow)      * SKP + kcol]);
                ldsm4(t1, &sBh[(nrow + 16) * SKP + kcol]);
                ldsm4(u0, &sBl[(nrow)      * SKP + kcol]);
                ldsm4(u1, &sBl[(nrow + 16) * SKP + kcol]);
                bh[0][0]=t0[0]; bh[0][1]=t0[1]; bh[1][0]=t0[2]; bh[1][1]=t0[3];
                bh[2][0]=t1[0]; bh[2][1]=t1[1]; bh[3][0]=t1[2]; bh[3][1]=t1[3];
                bl[0][0]=u0[0]; bl[0][1]=u0[1]; bl[1][0]=u0[2]; bl[1][1]=u0[3];
                bl[2][0]=u1[0]; bl[2][1]=u1[1]; bl[3][0]=u1[2]; bl[3][1]=u1[3];
            }
            #pragma unroll
            for (int i = 0; i < 2; ++i)
                #pragma unroll
                for (int j = 0; j < 4; ++j) {
                    mma16816(acc[i][j], ah[i], bh[j]);
                    mma16816(acc[i][j], al[i], bh[j]);
                    mma16816(acc[i][j], ah[i], bl[j]);
                }
        }
        __syncthreads();
    }
    #pragma unroll
    for (int i = 0; i < 2; ++i) {
        int r = wm*32 + i*16 + (lane >> 2);
        #pragma unroll
        for (int j = 0; j < 4; ++j) {
            int cc = wn*32 + j*8 + (lane & 3)*2;
            Cs[r*68 + cc]         = acc[i][j][0];
            Cs[r*68 + cc + 1]     = acc[i][j][1];
            Cs[(r+8)*68 + cc]     = acc[i][j][2];
            Cs[(r+8)*68 + cc + 1] = acc[i][j][3];
        }
    }
    __syncthreads();
    for (int idx = tid; idx < 96*64; idx += 192) {
        int r = idx >> 6, cc = idx & 63;
        float v = Cs[r*68 + cc] + bias[n0 + cc];
        if (ACT) v = tanh_fast(v);
        Out[(size_t)(m0 + r)*256 + n0 + cc] = v;
    }
}

// ------------------ persistent pure-fp16 scan -----------------------------------
__global__ __launch_bounds__(PTHREADS, 1)
void lstm_persist(const __half* __restrict__ Xh, const __half* __restrict__ Wh,
                  const float* __restrict__ bias, const float* __restrict__ Gmat,
                  const float* __restrict__ Cinit,
                  __half* __restrict__ GhH, __half* __restrict__ GhL)
{
    extern __shared__ __align__(16) char sm[];
    __half* sWh  = (__half*)(sm + SM_WH);
    float* sG    = (float*)(sm + SM_G);
    float* sBias = (float*)(sm + SM_BIAS);
    float* Hs    = (float*)(sm + SM_HS);
    const uint32_t smu = (uint32_t)__cvta_generic_to_shared(sm);

    const int tid = threadIdx.x, lane = tid & 31, warp = tid >> 5;
    const int wr = warp >> 2, wg = warp & 3;
    const int grp = blockIdx.x >> 3, nc = blockIdx.x & 7;
    const int m0 = grp*96, n0 = nc*128, u0 = nc*32;
    const int p = lane & 1;

    // one-time: Wh cache, G, bias, c (fragment layout)
    for (int e = tid; e < 128*64; e += PTHREADS) {
        int r = e >> 6, kq = (e & 63) * 8;
        *(uint4*)&sWh[r*WSTR + kq] = *(const uint4*)(Wh + (size_t)(n0 + r)*KCAT + kq);
    }
    for (int i = tid; i < NN*NN; i += PTHREADS) sG[i] = Gmat[i];
    if (tid < 128) sBias[tid] = bias[n0 + tid];
    float creg[8];
    #pragma unroll
    for (int i = 0; i < 2; ++i)
        #pragma unroll
        for (int j = 0; j < 4; ++j) {
            int row = wr*32 + i*16 + (lane >> 2) + 8*p;
            int uu  = wg*8 + 2*j + ((lane & 3) >> 1);
            creg[i*4 + j] = Cinit[(m0 + row)*HH + u0 + uu];
        }
    __syncthreads();

    const int ar = tid >> 2, ak = (tid & 3) * 16;
    // epilogue node-mix mapping: one row, octet of units per thread
    const int er = tid >> 2, eu = (tid & 3) * 8;
    const int elb = er / NN, en = er - elb * NN;

    auto issue = [&](const __half* src, int kk, int buf) {
        uint32_t sb = smu + SM_STAGE + buf*BUFB + (ar*ASTR + ak)*2;
        const __half* gp = src + (size_t)(m0 + ar)*256 + kk + ak;
        cp16(sb, gp);
        cp16(sb + 16, gp + 8);
        asm volatile("cp.async.commit_group;");
    };

    issue(Xh, 0, 0);   // prefetch t=0 phase-1 chunk0

    for (int t = 0; t < TT; ++t) {
        const int pi = t & 1, po = pi ^ 1;
        const __half* XhT = Xh + (size_t)t*ROWS*FF;
        const __half* GhHp = GhH + (size_t)pi*ROWS*HH;

        float acc[2][4][4];
        #pragma unroll
        for (int i = 0; i < 2; ++i)
            #pragma unroll
            for (int j = 0; j < 4; ++j)
                #pragma unroll
                for (int e = 0; e < 4; ++e) acc[i][j][e] = 0.f;

        auto compute = [&](int kw, int buf) {
            const __half* sB = (const __half*)(sm + SM_STAGE + buf*BUFB);
            #pragma unroll
            for (int kq = 0; kq < 64; kq += 16) {
                unsigned a[2][4], w[4][2];
                #pragma unroll
                for (int i = 0; i < 2; ++i) {
                    int row = wr*32 + i*16 + (lane & 15);
                    int col = kq + ((lane >> 4) << 3);
                    ldsm4(a[i], &sB[row*ASTR + col]);
                }
                #pragma unroll
                for (int j2 = 0; j2 < 2; ++j2) {
                    int g = lane >> 3, r = lane & 7;
                    int grow = wg*32 + j2*16 + ((g >> 1) << 3) + r;
                    int kcol = kw + kq + ((g & 1) << 3);
                    unsigned tw[4];
                    ldsm4(tw, &sWh[grow*WSTR + kcol]);
                    w[j2*2][0]   = tw[0]; w[j2*2][1]   = tw[1];
                    w[j2*2+1][0] = tw[2]; w[j2*2+1][1] = tw[3];
                }
                #pragma unroll
                for (int i = 0; i < 2; ++i)
                    #pragma unroll
                    for (int j = 0; j < 4; ++j)
                        mma16816(acc[i][j], a[i], w[j]);
            }
        };

        // phase 1: k [0,256) from x(t)
        #pragma unroll
        for (int c = 0; c < 4; ++c) {
            asm volatile("cp.async.wait_group 0;" ::: "memory");
            __syncthreads();
            if (c < 3) issue(XhT, (c + 1)*64, (c + 1) & 1);
            compute(c*64, c & 1);
        }
        // wait for all 8 peers to have published Gh(t)
        if (t > 0) {
            if (tid == 0) {
                unsigned v, tgt = 8u * (unsigned)t;
                while (1) {
                    asm volatile("ld.acquire.gpu.global.u32 %0, [%1];"
                                 : "=r"(v) : "l"(&g_bar[grp]) : "memory");
                    if (v >= tgt) break;
                    __nanosleep(32);
                }
            }
            __syncthreads();
        }
        // phase 2: k [256,512) from Gh(t)
        issue(GhHp, 0, 0);
        #pragma unroll
        for (int c = 0; c < 4; ++c) {
            asm volatile("cp.async.wait_group 0;" ::: "memory");
            __syncthreads();
            if (c < 3) issue(GhHp, (c + 1)*64, (c + 1) & 1);
            compute(256 + c*64, c & 1);
        }

        // prefetch next step's phase-1 chunk0 during epilogue
        if (t + 1 < TT) issue(XhT + ROWS*FF, 0, 0);

        // ---- fused epilogue: shfl-quad + LSTM cell (c in regs) ----
        #pragma unroll
        for (int i = 0; i < 2; ++i)
            #pragma unroll
            for (int j = 0; j < 4; ++j) {
                float d0 = acc[i][j][0], d1 = acc[i][j][1];
                float d2 = acc[i][j][2], d3 = acc[i][j][3];
                float s0 = __shfl_xor_sync(0xffffffffu, p ? d0 : d2, 1);
                float s1 = __shfl_xor_sync(0xffffffffu, p ? d1 : d3, 1);
                float qi = p ? s0 : d0, qf = p ? s1 : d1;
                float qg = p ? d2 : s0, qo = p ? d3 : s1;
                int row = wr*32 + i*16 + (lane >> 2) + 8*p;
                int uu  = wg*8 + 2*j + ((lane & 3) >> 1);
                float4 bv = *(const float4*)&sBias[4*uu];
                float vi = sigf(qi + bv.x);
                float vf = sigf(qf + bv.y);
                float vg = tanh_fast(qg + bv.z);
                float vo = sigf(qo + bv.w);
                float cv = vf * creg[i*4 + j] + vi * vg;
                creg[i*4 + j] = cv;
                Hs[row*HSTR + uu] = vo * tanh_fast(cv);
            }
        __syncthreads();
        // node-mix fresh h -> Gh(po): one row x 8 units per thread, vectorized
        {
            float4 A = {0.f, 0.f, 0.f, 0.f}, B4 = {0.f, 0.f, 0.f, 0.f};
            const float* gr = &sG[en*NN];
            #pragma unroll
            for (int m = 0; m < NN; ++m) {
                float g = gr[m];
                const float4* hp = (const float4*)&Hs[(elb*NN + m)*HSTR + eu];
                float4 h0 = hp[0], h1 = hp[1];
                A.x += g*h0.x; A.y += g*h0.y; A.z += g*h0.z; A.w += g*h0.w;
                B4.x += g*h1.x; B4.y += g*h1.y; B4.z += g*h1.z; B4.w += g*h1.w;
            }
            uint4 hv;
            hv.x = pack2h(A.x, A.y);  hv.y = pack2h(A.z, A.w);
            hv.z = pack2h(B4.x, B4.y); hv.w = pack2h(B4.z, B4.w);
            size_t off = (size_t)(m0 + er)*HH + u0 + eu;
            *(uint4*)(GhH + (size_t)po*ROWS*HH + off) = hv;
            if (t == TT - 1) {   // lo residual for final fc GEMM
                const __half* hb = (const __half*)&hv;
                float lo[8] = {
                    A.x  - __half2float(hb[0]), A.y  - __half2float(hb[1]),
                    A.z  - __half2float(hb[2]), A.w  - __half2float(hb[3]),
                    B4.x - __half2float(hb[4]), B4.y - __half2float(hb[5]),
                    B4.z - __half2float(hb[6]), B4.w - __half2float(hb[7]) };
                uint4 lv;
                lv.x = pack2h(lo[0], lo[1]); lv.y = pack2h(lo[2], lo[3]);
                lv.z = pack2h(lo[4], lo[5]); lv.w = pack2h(lo[6], lo[7]);
                *(uint4*)(GhL + off) = lv;
            }
        }
        __syncthreads();
        if (tid == 0)
            asm volatile("red.release.gpu.global.add.u32 [%0], %1;"
                         :: "l"(&g_bar[grp]), "r"(1u) : "memory");
    }
}

// ---------------------------------------------------------------------------
extern "C" void kernel_launch(void* const* d_in, const int* in_sizes, int n_in,
                              void* d_out, int out_size)
{
    const float* x    = (const float*)d_in[0];
    const float* G    = (const float*)d_in[1];
    const float* W_ih = (const float*)d_in[2];
    const float* b_ih = (const float*)d_in[3];
    const float* W_hh = (const float*)d_in[4];
    const float* b_hh = (const float*)d_in[5];
    const float* W_h1 = (const float*)d_in[6];
    const float* b_h1 = (const float*)d_in[7];
    const float* W_h2 = (const float*)d_in[8];
    const float* b_h2 = (const float*)d_in[9];
    const float* W_fc = (const float*)d_in[10];
    const float* b_fc = (const float*)d_in[11];
    float* out = (float*)d_out;

    __half *Xh, *Xl, *Ghh, *Ghl, *Wch, *W1h, *W1l, *W2h, *W2l, *Wfh, *Wfl;
    float *bcat, *h, *c;
    cudaGetSymbolAddress((void**)&Xh,  g_Xh);
    cudaGetSymbolAddress((void**)&Xl,  g_Xl);
    cudaGetSymbolAddress((void**)&Ghh, g_Ghh);
    cudaGetSymbolAddress((void**)&Ghl, g_Ghl);
    cudaGetSymbolAddress((void**)&Wch, g_Wch);
    cudaGetSymbolAddress((void**)&W1h, g_W1h);
    cudaGetSymbolAddress((void**)&W1l, g_W1l);
    cudaGetSymbolAddress((void**)&W2h, g_W2h);
    cudaGetSymbolAddress((void**)&W2l, g_W2l);
    cudaGetSymbolAddress((void**)&Wfh, g_Wfh);
    cudaGetSymbolAddress((void**)&Wfl, g_Wfl);
    cudaGetSymbolAddress((void**)&bcat, g_bcat);
    cudaGetSymbolAddress((void**)&h,   g_h);
    cudaGetSymbolAddress((void**)&c,   g_c);

    cudaFuncSetAttribute(lstm_persist, cudaFuncAttributeMaxDynamicSharedMemorySize, SM_TOTAL);

    // prep
    mix_x<<<BB*TT, 256>>>(x, G);
    pack_cat<<<(G4H*KCAT)/256, 256>>>(W_ih, W_hh, b_ih, b_hh);
    pack_all<<<768, 256>>>(W_h1, W_h2, W_fc);

    // h0 and c0 concurrently (z selects weight/bias/output)
    mma_small<0><<<dim3(4, 16, 2), 192>>>(Xh, Xl,
                                          W1h, W1l, b_h1, h,
                                          W2h, W2l, b_h2, c);
    mix_h<<<BB, 256>>>(G, Ghh);   // Gh(0) hi -> buffer 0

    // persistent pure-fp16 scan (50 steps)
    lstm_persist<<<128, PTHREADS, SM_TOTAL>>>(Xh, Wch, bcat, G, c, Ghh, Ghl);

    // output: tanh((G h) @ W_fc^T + b_fc); after 50 steps Gh is in buffer 0
    mma_small<1><<<dim3(4, 16, 1), 192>>>(Ghh, Ghl,
                                          Wfh, Wfl, b_fc, out,
                                          Wfh, Wfl, b_fc, out);
}